// round 7
// baseline (speedup 1.0000x reference)
#include <cuda_runtime.h>
#include <cstdint>

// ---------------------------------------------------------------------------
// LocalGate: N=131072 tokens, D=1024, E=64, K=2, GATE_ST.
// Outputs (float32, concatenated):
//   [0,262144) token_ordering | [262144,524288) reversed_ordering
//   [524288,786432) cw (==1.0) | [786432,786496) input_splits
//   [786496,9175104) probs [N,64]
// GEMM numerics (bitwise-matched to XLA:CPU Eigen gebp fp32):
//   logit = fl( chain_fp32(k=0..511) + chain_fp32(k=512..1023) )
// Mainloop: pure FFMA2 (fma.rn.f32x2); B stored duplicated in smem so both
// operands come straight out of LDS.128 as aligned pairs (no packing movs).
// ---------------------------------------------------------------------------

#define NTOK      131072
#define MDIM      1024
#define NEXP      64
#define NK        (NTOK * 2)

#define TM        128      // tokens per block
#define KC        16       // k-chunk
#define NCHUNK    (MDIM / KC)
#define HALF_CH   (NCHUNK / 2)   // Eigen panel boundary (512 k)
#define AS        132      // smem A row stride (128 + 4, 16B-aligned)
#define BSD       132      // smem B-dup row stride (128 dup + 4)

#define SORT_BLOCKS 512
#define SORT_CHUNK  (NK / SORT_BLOCKS)   // 512 (== 2 gate blocks)

__device__ unsigned char g_flat[NK];
__device__ int           g_bh[SORT_BLOCKS * NEXP];
__device__ int           g_start[NEXP];

// packed fp32 FMA: 2 IEEE-rn FMAs per instruction (per-lane identical to FFMA)
__device__ __forceinline__ void ffma2(float2& d, const float2& a, const float2& b) {
    asm("fma.rn.f32x2 %0, %1, %2, %0;"
        : "+l"(*reinterpret_cast<unsigned long long*>(&d))
        : "l"(*reinterpret_cast<const unsigned long long*>(&a)),
          "l"(*reinterpret_cast<const unsigned long long*>(&b)));
}

__global__ void __launch_bounds__(256, 2)
gate_kernel(const float* __restrict__ X, const float* __restrict__ W,
            float* __restrict__ probs_out, float* __restrict__ cw_out)
{
    __shared__ __align__(16) union SM {
        struct { float A[2][KC * AS]; float B[2][KC * BSD]; } g;
        struct { float L[TM * 65]; float inv[TM]; } e;
    } sm;
    __shared__ int h[NEXP];

    const int t    = threadIdx.x;
    const int tok0 = blockIdx.x * TM;
    const int tx   = t & 15;     // token oct (8 tokens)
    const int ty   = t >> 4;     // expert quad (4 experts)

    if (t < NEXP) h[t] = 0;      // fused-histogram counters

    const int lr  = t >> 2;      // 0..63
    const int lk4 = t & 3;       // 0..3
    const float* xr0 = X + (size_t)(tok0 + lr) * MDIM + lk4 * 4;
    const float* xr1 = X + (size_t)(tok0 + 64 + lr) * MDIM + lk4 * 4;
    const float* wr  = W + (size_t)lr * MDIM + lk4 * 4;
    const int oA = (lk4 * 4) * AS + lr;
    const int oB = (lk4 * 4) * BSD + lr * 2;   // duplicated pair slot

    // two Eigen panels: accL covers k in [0,512), accH covers [512,1024)
    float2 accL[4][4], accH[4][4];
    #pragma unroll
    for (int p = 0; p < 4; ++p)
        #pragma unroll
        for (int j = 0; j < 4; ++j) {
            accL[p][j] = make_float2(0.f, 0.f);
            accH[p][j] = make_float2(0.f, 0.f);
        }

    // prefetch chunk 0
    float4 na0 = *(const float4*)(xr0);
    float4 na1 = *(const float4*)(xr1);
    float4 nb  = *(const float4*)(wr);
    {
        float* A0 = sm.g.A[0]; float* B0 = sm.g.B[0];
        A0[oA + 0*AS] = na0.x; A0[oA + 1*AS] = na0.y; A0[oA + 2*AS] = na0.z; A0[oA + 3*AS] = na0.w;
        A0[oA + 0*AS + 64] = na1.x; A0[oA + 1*AS + 64] = na1.y;
        A0[oA + 2*AS + 64] = na1.z; A0[oA + 3*AS + 64] = na1.w;
        *(float2*)(B0 + oB + 0*BSD) = make_float2(nb.x, nb.x);
        *(float2*)(B0 + oB + 1*BSD) = make_float2(nb.y, nb.y);
        *(float2*)(B0 + oB + 2*BSD) = make_float2(nb.z, nb.z);
        *(float2*)(B0 + oB + 3*BSD) = make_float2(nb.w, nb.w);
    }
    __syncthreads();

    for (int c = 0; c < NCHUNK; ++c) {
        const int buf = c & 1;
        const bool pre = (c + 1 < NCHUNK);
        if (pre) {
            const int kc = (c + 1) * KC;
            na0 = *(const float4*)(xr0 + kc);
            na1 = *(const float4*)(xr1 + kc);
            nb  = *(const float4*)(wr  + kc);
        }
        const float* Ab = sm.g.A[buf];
        const float* Bb = sm.g.B[buf];
        float2 (*acc)[4] = (c < HALF_CH) ? accL : accH;
        #pragma unroll
        for (int k = 0; k < KC; ++k) {
            const float4 a0 = *(const float4*)(Ab + k * AS + tx * 8);
            const float4 a1 = *(const float4*)(Ab + k * AS + tx * 8 + 4);
            const float4 b0 = *(const float4*)(Bb + k * BSD + ty * 8);
            const float4 b1 = *(const float4*)(Bb + k * BSD + ty * 8 + 4);
            const float2* ap0 = reinterpret_cast<const float2*>(&a0);  // in-bounds aliases only
            const float2* ap1 = reinterpret_cast<const float2*>(&a1);
            const float2* bp0 = reinterpret_cast<const float2*>(&b0);
            const float2* bp1 = reinterpret_cast<const float2*>(&b1);
            #pragma unroll
            for (int p = 0; p < 2; ++p) {
                ffma2(acc[p][0], ap0[p], bp0[0]);
                ffma2(acc[p][1], ap0[p], bp0[1]);
                ffma2(acc[p][2], ap0[p], bp1[0]);
                ffma2(acc[p][3], ap0[p], bp1[1]);
            }
            #pragma unroll
            for (int p = 0; p < 2; ++p) {
                ffma2(acc[2 + p][0], ap1[p], bp0[0]);
                ffma2(acc[2 + p][1], ap1[p], bp0[1]);
                ffma2(acc[2 + p][2], ap1[p], bp1[0]);
                ffma2(acc[2 + p][3], ap1[p], bp1[1]);
            }
        }
        if (pre) {
            float* An = sm.g.A[buf ^ 1]; float* Bn = sm.g.B[buf ^ 1];
            An[oA + 0*AS] = na0.x; An[oA + 1*AS] = na0.y; An[oA + 2*AS] = na0.z; An[oA + 3*AS] = na0.w;
            An[oA + 0*AS + 64] = na1.x; An[oA + 1*AS + 64] = na1.y;
            An[oA + 2*AS + 64] = na1.z; An[oA + 3*AS + 64] = na1.w;
            *(float2*)(Bn + oB + 0*BSD) = make_float2(nb.x, nb.x);
            *(float2*)(Bn + oB + 1*BSD) = make_float2(nb.y, nb.y);
            *(float2*)(Bn + oB + 2*BSD) = make_float2(nb.z, nb.z);
            *(float2*)(Bn + oB + 3*BSD) = make_float2(nb.w, nb.w);
        }
        __syncthreads();
    }

    // ---- epilogue: logits = panelL + panelH -> smem ----
    #pragma unroll
    for (int p = 0; p < 4; ++p) {
        const int tokA = tx * 8 + p * 2;
        #pragma unroll
        for (int j = 0; j < 4; ++j) {
            const int e = ty * 4 + j;
            sm.e.L[tokA * 65 + e]       = accL[p][j].x + accH[p][j].x;
            sm.e.L[(tokA + 1) * 65 + e] = accL[p][j].y + accH[p][j].y;
        }
    }
    __syncthreads();

    if (t < TM) {
        float* row = &sm.e.L[t * 65];
        float v1 = -1e30f, v2 = -1e30f; int i1 = 0, i2 = 0;
        #pragma unroll
        for (int e = 0; e < NEXP; ++e) {
            float v = row[e];
            if (v > v1)      { v2 = v1; i2 = i1; v1 = v; i1 = e; }
            else if (v > v2) { v2 = v;  i2 = e; }
        }
        g_flat[(size_t)(tok0 + t) * 2]     = (unsigned char)i1;
        g_flat[(size_t)(tok0 + t) * 2 + 1] = (unsigned char)i2;
        atomicAdd(&h[i1], 1);
        atomicAdd(&h[i2], 1);
        float s = 0.f;
        #pragma unroll
        for (int e = 0; e < NEXP; ++e) {
            float ex = __expf(row[e] - v1);
            s += ex;
            row[e] = ex;
        }
        sm.e.inv[t] = 1.0f / s;
    }
    __syncthreads();

    float* pbase = probs_out + (size_t)tok0 * NEXP;
    #pragma unroll
    for (int q = 0; q < (TM * NEXP) / 256; ++q) {
        const int idx = t + q * 256;
        const int r = idx >> 6, cix = idx & 63;
        pbase[idx] = sm.e.L[r * 65 + cix] * sm.e.inv[r];
    }
    cw_out[2 * tok0 + t] = 1.0f;            // straight-through forward value
    if (t < NEXP) atomicAdd(&g_bh[(blockIdx.x >> 1) * NEXP + t], h[t]);
}

// ---------------------------------------------------------------------------
__global__ void zero_bh_kernel()
{
    const int i = blockIdx.x * 1024 + threadIdx.x;
    if (i < SORT_BLOCKS * NEXP) g_bh[i] = 0;
}

// 1 block, 1024 threads: warp w handles experts 2w, 2w+1 across 512 chunks
__global__ void scan_kernel(float* __restrict__ splits_out)
{
    __shared__ int tot[NEXP];
    const int w    = threadIdx.x >> 5;
    const int lane = threadIdx.x & 31;
    #pragma unroll
    for (int ee = 0; ee < 2; ++ee) {
        const int e = w * 2 + ee;
        int v[16], s = 0;
        #pragma unroll
        for (int i = 0; i < 16; ++i) v[i] = g_bh[(lane * 16 + i) * NEXP + e];
        #pragma unroll
        for (int i = 0; i < 16; ++i) { const int x = v[i]; v[i] = s; s += x; }
        int run = s;
        #pragma unroll
        for (int off = 1; off < 32; off <<= 1) {
            const int n = __shfl_up_sync(0xffffffffu, run, off);
            if (lane >= off) run += n;
        }
        const int excl = run - s;
        #pragma unroll
        for (int i = 0; i < 16; ++i) g_bh[(lane * 16 + i) * NEXP + e] = v[i] + excl;
        if (lane == 31) tot[e] = run;
    }
    __syncthreads();
    if (threadIdx.x < NEXP) splits_out[threadIdx.x] = (float)tot[threadIdx.x];
    if (threadIdx.x == 0) {
        int base = 0;
        for (int e = 0; e < NEXP; ++e) { g_start[e] = base; base += tot[e]; }
    }
}

__global__ void rank_kernel(float* __restrict__ to_out, float* __restrict__ ro_out)
{
    __shared__ int cnt[NEXP];
    const int lane = threadIdx.x;            // 32 threads (one warp, stable order)
    cnt[lane]      = g_start[lane]      + g_bh[blockIdx.x * NEXP + lane];
    cnt[lane + 32] = g_start[lane + 32] + g_bh[blockIdx.x * NEXP + lane + 32];
    __syncwarp();
    const int base = blockIdx.x * SORT_CHUNK;
    #pragma unroll
    for (int it = 0; it < SORT_CHUNK / 32; ++it) {
        const int i = base + it * 32 + lane;
        const int e = g_flat[i];
        const unsigned peers = __match_any_sync(0xffffffffu, e);
        const int leader = __ffs(peers) - 1;
        const int prior  = __popc(peers & ((1u << lane) - 1));
        int b = 0;
        if (lane == leader) b = atomicAdd(&cnt[e], __popc(peers));
        b = __shfl_sync(peers, b, leader);
        const int p = b + prior;
        to_out[p] = (float)(i >> 1);         // dispatch slot -> source token
        ro_out[i] = (float)p;                // flat slot -> rank
    }
}

// ---------------------------------------------------------------------------
extern "C" void kernel_launch(void* const* d_in, const int* in_sizes, int n_in,
                              void* d_out, int out_size)
{
    const float* X = (const float*)d_in[0];   // [131072, 1024]
    const float* W = (const float*)d_in[1];   // [64, 1024]
    float* out = (float*)d_out;

    float* TO  = out;                 // token_ordering
    float* RO  = out + NK;            // reversed_ordering
    float* CW  = out + 2 * NK;        // cw (all 1.0)
    float* SPL = out + 3 * NK;        // input_splits
    float* PR  = out + 3 * NK + NEXP; // probs [N, E]

    zero_bh_kernel<<<(SORT_BLOCKS * NEXP + 1023) / 1024, 1024>>>();
    gate_kernel<<<NTOK / TM, 256>>>(X, W, PR, CW);
    scan_kernel<<<1, 1024>>>(SPL);
    rank_kernel<<<SORT_BLOCKS, 32>>>(TO, RO);
}

// round 8
// speedup vs baseline: 1.7768x; 1.7768x over previous
#include <cuda_runtime.h>
#include <cstdint>

// ---------------------------------------------------------------------------
// LocalGate: N=131072 tokens, D=1024, E=64, K=2, GATE_ST.
// Strategy:
//   1) gate: tf32 mma.sync GEMM (RNA operands) -> probs (err ~5.7e-4 < 1e-3),
//      fast top-3; flag near-tie tokens (gap < TAU).
//   2) repair: recompute flagged tokens' logits EXACTLY (Eigen two-panel fp32
//      chain, bitwise = reference) and overwrite their top-2.
//   3) counting sort (hist/scan/rank) on repaired assignments.
// ---------------------------------------------------------------------------

#define NTOK  131072
#define MDIM  1024
#define NEXP  64
#define NK    (NTOK * 2)
#define TM    128
#define KC    32
#define NCH   (MDIM / KC)           // 32
#define ASTR  36
#define STGF  ((TM + NEXP) * ASTR)  // 6912 floats
#define STGB  (STGF * 4)
#define NSTG  3
#define GK_SMEM (NSTG * STGB)       // 82944

#define TAU   2.5e-3f

#define SORT_BLOCKS 512
#define SORT_CHUNK  (NK / SORT_BLOCKS)  // 512

#define FIX_PER_BLK 32
#define REPAIR_BLOCKS 128
// repair smem: X 32x1024 + W 8x1024 + logits 32x64 (floats)
#define RP_XS   0
#define RP_WS   (32 * 1024)
#define RP_LG   (RP_WS + 8 * 1024)
#define RP_SMEM ((RP_LG + 32 * 64) * 4)   // 172 KB

__device__ unsigned char g_flat[NK];
__device__ int           g_bh[SORT_BLOCKS * NEXP];
__device__ int           g_start[NEXP];
__device__ int           g_fix[NTOK];
__device__ int           g_nfix;

__device__ __forceinline__ uint32_t smem_u32(const void* p) {
    uint32_t a;
    asm("{ .reg .u64 t; cvta.to.shared.u64 t, %1; cvt.u32.u64 %0, t; }" : "=r"(a) : "l"(p));
    return a;
}
__device__ __forceinline__ uint32_t tf32_rna(float x) {
    uint32_t r; asm("cvt.rna.tf32.f32 %0, %1;" : "=r"(r) : "f"(x)); return r;
}
__device__ __forceinline__ void cp16(uint32_t dst, const void* src) {
    asm volatile("cp.async.cg.shared.global [%0], [%1], 16;" :: "r"(dst), "l"(src) : "memory");
}
__device__ __forceinline__ void mma_tf32(float* d, const uint32_t* a, const uint32_t* b) {
    asm volatile(
        "mma.sync.aligned.m16n8k8.row.col.f32.tf32.tf32.f32 "
        "{%0,%1,%2,%3}, {%4,%5,%6,%7}, {%8,%9}, {%0,%1,%2,%3};"
        : "+f"(d[0]), "+f"(d[1]), "+f"(d[2]), "+f"(d[3])
        : "r"(a[0]), "r"(a[1]), "r"(a[2]), "r"(a[3]), "r"(b[0]), "r"(b[1]));
}

__device__ __forceinline__ void issue_chunk(uint32_t sbase, int s,
                                            const float* __restrict__ X,
                                            const float* __restrict__ W,
                                            int tok0, int c, int t)
{
    const int r  = t >> 3;
    const int k4 = t & 7;
    const uint32_t stg = sbase + (uint32_t)s * STGB;
    const uint32_t adst = stg + r * (ASTR * 4) + k4 * 16;
    const float* xs = X + (size_t)(tok0 + r) * MDIM + c * KC + k4 * 4;
    #pragma unroll
    for (int i = 0; i < 8; ++i)
        cp16(adst + i * 16 * (ASTR * 4), xs + (size_t)i * 16 * MDIM);
    const uint32_t bdst = stg + (TM + r) * (ASTR * 4) + k4 * 16;
    const float* ws = W + (size_t)r * MDIM + c * KC + k4 * 4;
    #pragma unroll
    for (int i = 0; i < 4; ++i)
        cp16(bdst + i * 16 * (ASTR * 4), ws + (size_t)i * 16 * MDIM);
    asm volatile("cp.async.commit_group;" ::: "memory");
}

__global__ void __launch_bounds__(128, 2)
gate_kernel(const float* __restrict__ X, const float* __restrict__ W,
            float* __restrict__ probs_out, float* __restrict__ cw_out)
{
    extern __shared__ float smf[];
    __shared__ float inv[TM];
    const uint32_t sbase = smem_u32(smf);
    const int t    = threadIdx.x;
    const int wid  = t >> 5;
    const int lane = t & 31;
    const int tok0 = blockIdx.x * TM;

    float acc[2][8][4];
    #pragma unroll
    for (int mt = 0; mt < 2; ++mt)
        #pragma unroll
        for (int nt = 0; nt < 8; ++nt)
            #pragma unroll
            for (int i = 0; i < 4; ++i) acc[mt][nt][i] = 0.f;

    issue_chunk(sbase, 0, X, W, tok0, 0, t);
    issue_chunk(sbase, 1, X, W, tok0, 1, t);

    const int ar = lane >> 2;
    const int ac = lane & 3;

    for (int c = 0; c < NCH; ++c) {
        if (c == NCH - 1) asm volatile("cp.async.wait_group 0;" ::: "memory");
        else              asm volatile("cp.async.wait_group 1;" ::: "memory");
        __syncthreads();
        if (c + 2 < NCH) issue_chunk(sbase, (c + 2) % NSTG, X, W, tok0, c + 2, t);

        const float* Ab = smf + (size_t)(c % NSTG) * STGF;
        const float* Bb = Ab + TM * ASTR;
        #pragma unroll
        for (int ks = 0; ks < 4; ++ks) {
            const int k0 = ks * 8 + ac;
            uint32_t a[2][4], b[8][2];
            #pragma unroll
            for (int mt = 0; mt < 2; ++mt) {
                const float* ap = Ab + (wid * 32 + mt * 16 + ar) * ASTR + k0;
                a[mt][0] = tf32_rna(ap[0]);
                a[mt][1] = tf32_rna(ap[8 * ASTR]);
                a[mt][2] = tf32_rna(ap[4]);
                a[mt][3] = tf32_rna(ap[8 * ASTR + 4]);
            }
            #pragma unroll
            for (int nt = 0; nt < 8; ++nt) {
                const float* bp = Bb + (nt * 8 + ar) * ASTR + k0;
                b[nt][0] = tf32_rna(bp[0]);
                b[nt][1] = tf32_rna(bp[4]);
            }
            #pragma unroll
            for (int mt = 0; mt < 2; ++mt)
                #pragma unroll
                for (int nt = 0; nt < 8; ++nt)
                    mma_tf32(acc[mt][nt], a[mt], b[nt]);
        }
    }
    __syncthreads();                 // all MMA smem reads done -> overlay logits

    float* L = smf;                  // [128][65]
    #pragma unroll
    for (int mt = 0; mt < 2; ++mt) {
        const int r0 = wid * 32 + mt * 16 + ar;
        #pragma unroll
        for (int nt = 0; nt < 8; ++nt) {
            const int n0 = nt * 8 + ac * 2;
            L[r0 * 65 + n0]           = acc[mt][nt][0];
            L[r0 * 65 + n0 + 1]       = acc[mt][nt][1];
            L[(r0 + 8) * 65 + n0]     = acc[mt][nt][2];
            L[(r0 + 8) * 65 + n0 + 1] = acc[mt][nt][3];
        }
    }
    __syncthreads();

    {   // per-token: fast top-3, flag near-ties for exact repair
        float* row = L + t * 65;
        float v1 = -1e30f, v2 = -1e30f, v3 = -1e30f; int i1 = 0, i2 = 0;
        #pragma unroll
        for (int e = 0; e < NEXP; ++e) {
            const float v = row[e];
            if (v > v1)      { v3 = v2; v2 = v1; i2 = i1; v1 = v; i1 = e; }
            else if (v > v2) { v3 = v2; v2 = v;  i2 = e; }
            else if (v > v3) { v3 = v; }
        }
        const int tok = tok0 + t;
        g_flat[(size_t)tok * 2]     = (unsigned char)i1;
        g_flat[(size_t)tok * 2 + 1] = (unsigned char)i2;
        if ((v1 - v2 < TAU) || (v2 - v3 < TAU)) {
            const int j = atomicAdd(&g_nfix, 1);
            if (j < NTOK) g_fix[j] = tok;
        }
        float s = 0.f;
        #pragma unroll
        for (int e = 0; e < NEXP; ++e) {
            const float ex = __expf(row[e] - v1);
            s += ex;
            row[e] = ex;
        }
        inv[t] = 1.0f / s;
    }
    __syncthreads();

    float* pbase = probs_out + (size_t)tok0 * NEXP;
    #pragma unroll
    for (int q = 0; q < (TM * NEXP) / 128; ++q) {
        const int idx = t + q * 128;
        pbase[idx] = L[(idx >> 6) * 65 + (idx & 63)] * inv[idx >> 6];
    }
    cw_out[2 * tok0 + t]       = 1.0f;   // straight-through forward value
    cw_out[2 * tok0 + 128 + t] = 1.0f;
}

// ---------------------------------------------------------------------------
__global__ void reset_kernel() { if (threadIdx.x == 0) g_nfix = 0; }

// Exact (bitwise-reference) recompute of flagged tokens:
//   logit = fl( chain_fp32(k<512) + chain_fp32(k>=512) )
__global__ void __launch_bounds__(256)
repair_kernel(const float* __restrict__ X, const float* __restrict__ W)
{
    extern __shared__ float rsm[];
    float* XS = rsm + RP_XS;      // [32][1024]
    float* WS = rsm + RP_WS;      // [8][1024]
    float* LG = rsm + RP_LG;      // [32][64]
    const int t  = threadIdx.x;
    const int ts = t >> 3;        // token slot 0..31
    const int el = t & 7;         // expert lane in group

    const int nf = g_nfix;
    for (int base = blockIdx.x * FIX_PER_BLK; base < nf; base += gridDim.x * FIX_PER_BLK) {
        const int nt = min(FIX_PER_BLK, nf - base);
        __syncthreads();
        // load X rows of flagged tokens
        for (int i = 0; i < 32; ++i) {
            const int idx = t + i * 256;          // 8192 float4 slots
            const int row = idx >> 8, c4 = idx & 255;
            if (row < nt) {
                const int tok = g_fix[base + row];
                *(float4*)(XS + row * 1024 + c4 * 4) =
                    *(const float4*)(X + (size_t)tok * MDIM + c4 * 4);
            }
        }
        for (int eg = 0; eg < 8; ++eg) {
            __syncthreads();
            // load W rows eg*8 .. eg*8+7
            #pragma unroll
            for (int i = 0; i < 8; ++i) {
                const int idx = t + i * 256;      // 2048 float4 slots
                const int row = idx >> 8, c4 = idx & 255;
                *(float4*)(WS + row * 1024 + c4 * 4) =
                    *(const float4*)(W + (size_t)(eg * 8 + row) * MDIM + c4 * 4);
            }
            __syncthreads();
            if (ts < nt) {
                const float* xr = XS + ts * 1024;
                const float* wr = WS + el * 1024;
                float a0 = 0.f, a1 = 0.f;
                for (int k = 0; k < 512; k += 4) {
                    const float4 x0 = *(const float4*)(xr + k);
                    const float4 w0 = *(const float4*)(wr + k);
                    const float4 x1 = *(const float4*)(xr + 512 + k);
                    const float4 w1 = *(const float4*)(wr + 512 + k);
                    a0 = fmaf(x0.x, w0.x, a0); a1 = fmaf(x1.x, w1.x, a1);
                    a0 = fmaf(x0.y, w0.y, a0); a1 = fmaf(x1.y, w1.y, a1);
                    a0 = fmaf(x0.z, w0.z, a0); a1 = fmaf(x1.z, w1.z, a1);
                    a0 = fmaf(x0.w, w0.w, a0); a1 = fmaf(x1.w, w1.w, a1);
                }
                LG[ts * 64 + eg * 8 + el] = a0 + a1;
            }
        }
        __syncthreads();
        if (t < nt) {
            const float* row = LG + t * 64;
            float v1 = -1e30f, v2 = -1e30f; int i1 = 0, i2 = 0;
            #pragma unroll
            for (int e = 0; e < NEXP; ++e) {
                const float v = row[e];
                if (v > v1)      { v2 = v1; i2 = i1; v1 = v; i1 = e; }
                else if (v > v2) { v2 = v;  i2 = e; }
            }
            const int tok = g_fix[base + t];
            g_flat[(size_t)tok * 2]     = (unsigned char)i1;
            g_flat[(size_t)tok * 2 + 1] = (unsigned char)i2;
        }
    }
}

// ---------------------------------------------------------------------------
// Counting sort (post-repair): hist -> scan -> rank
// ---------------------------------------------------------------------------
__global__ void hist_kernel()
{
    __shared__ int h[NEXP];
    const int t = threadIdx.x;       // 256 threads
    if (t < NEXP) h[t] = 0;
    __syncthreads();
    const int base = blockIdx.x * SORT_CHUNK;
    #pragma unroll
    for (int q = 0; q < SORT_CHUNK / 256; ++q)
        atomicAdd(&h[g_flat[base + t + q * 256]], 1);
    __syncthreads();
    if (t < NEXP) g_bh[blockIdx.x * NEXP + t] = h[t];
}

// 1 block, 1024 threads: warp w scans experts 2w, 2w+1 across 512 chunks
__global__ void scan_kernel(float* __restrict__ splits_out)
{
    __shared__ int tot[NEXP];
    const int w    = threadIdx.x >> 5;
    const int lane = threadIdx.x & 31;
    #pragma unroll
    for (int ee = 0; ee < 2; ++ee) {
        const int e = w * 2 + ee;
        int v[16], s = 0;
        #pragma unroll
        for (int i = 0; i < 16; ++i) v[i] = g_bh[(lane * 16 + i) * NEXP + e];
        #pragma unroll
        for (int i = 0; i < 16; ++i) { const int x = v[i]; v[i] = s; s += x; }
        int run = s;
        #pragma unroll
        for (int off = 1; off < 32; off <<= 1) {
            const int n = __shfl_up_sync(0xffffffffu, run, off);
            if (lane >= off) run += n;
        }
        const int excl = run - s;
        #pragma unroll
        for (int i = 0; i < 16; ++i) g_bh[(lane * 16 + i) * NEXP + e] = v[i] + excl;
        if (lane == 31) tot[e] = run;
    }
    __syncthreads();
    if (threadIdx.x < NEXP) splits_out[threadIdx.x] = (float)tot[threadIdx.x];
    if (threadIdx.x == 0) {
        int base = 0;
        for (int e = 0; e < NEXP; ++e) { g_start[e] = base; base += tot[e]; }
    }
}

__global__ void rank_kernel(float* __restrict__ to_out, float* __restrict__ ro_out)
{
    __shared__ int cnt[NEXP];
    const int lane = threadIdx.x;
    cnt[lane]      = g_start[lane]      + g_bh[blockIdx.x * NEXP + lane];
    cnt[lane + 32] = g_start[lane + 32] + g_bh[blockIdx.x * NEXP + lane + 32];
    __syncwarp();
    const int base = blockIdx.x * SORT_CHUNK;
    #pragma unroll
    for (int it = 0; it < SORT_CHUNK / 32; ++it) {
        const int i = base + it * 32 + lane;
        const int e = g_flat[i];
        const unsigned peers = __match_any_sync(0xffffffffu, e);
        const int leader = __ffs(peers) - 1;
        const int prior  = __popc(peers & ((1u << lane) - 1));
        int b = 0;
        if (lane == leader) b = atomicAdd(&cnt[e], __popc(peers));
        b = __shfl_sync(peers, b, leader);
        const int p = b + prior;
        to_out[p] = (float)(i >> 1);
        ro_out[i] = (float)p;
    }
}

// ---------------------------------------------------------------------------
extern "C" void kernel_launch(void* const* d_in, const int* in_sizes, int n_in,
                              void* d_out, int out_size)
{
    const float* X = (const float*)d_in[0];   // [131072, 1024]
    const float* W = (const float*)d_in[1];   // [64, 1024]
    float* out = (float*)d_out;

    float* TO  = out;
    float* RO  = out + NK;
    float* CW  = out + 2 * NK;
    float* SPL = out + 3 * NK;
    float* PR  = out + 3 * NK + NEXP;

    cudaFuncSetAttribute(gate_kernel, cudaFuncAttributeMaxDynamicSharedMemorySize, GK_SMEM);
    cudaFuncSetAttribute(repair_kernel, cudaFuncAttributeMaxDynamicSharedMemorySize, RP_SMEM);

    reset_kernel<<<1, 32>>>();
    gate_kernel<<<NTOK / TM, 128, GK_SMEM>>>(X, W, PR, CW);
    repair_kernel<<<REPAIR_BLOCKS, 256, RP_SMEM>>>(X, W);
    hist_kernel<<<SORT_BLOCKS, 256>>>();
    scan_kernel<<<1, 1024>>>(SPL);
    rank_kernel<<<SORT_BLOCKS, 32>>>(TO, RO);
}

// round 9
// speedup vs baseline: 1.8363x; 1.0335x over previous
#include <cuda_runtime.h>
#include <cstdint>

// ---------------------------------------------------------------------------
// LocalGate: N=131072 tokens, D=1024, E=64, K=2, GATE_ST.
// Strategy:
//   1) gate: tf32 mma.sync GEMM (RNA operands) -> probs (err ~2.8e-4 < 1e-3),
//      fast top-3; flag near-tie tokens (gap < TAU). 3-deep cp.async pipeline.
//   2) repair: recompute flagged tokens' logits EXACTLY (Eigen two-panel fp32
//      chain, bitwise = reference) and overwrite their top-2.
//   3) counting sort (hist/scan/rank) on repaired assignments.
// ---------------------------------------------------------------------------

#define NTOK  131072
#define MDIM  1024
#define NEXP  64
#define NK    (NTOK * 2)
#define TM    128
#define KC    32
#define NCH   (MDIM / KC)           // 32
#define ASTR  36
#define STGF  ((TM + NEXP) * ASTR)  // 6912 floats
#define STGB  (STGF * 4)
#define NSTG  4
#define GK_SMEM (NSTG * STGB)       // 110592

#define TAU   2.5e-3f

#define SORT_BLOCKS 512
#define SORT_CHUNK  (NK / SORT_BLOCKS)  // 512

#define FIX_PER_BLK 32
#define REPAIR_BLOCKS 128
// repair smem: X 32x1024 + W 16x1024 + logits 32x64 (floats)
#define RP_XS   0
#define RP_WS   (32 * 1024)
#define RP_LG   (RP_WS + 16 * 1024)
#define RP_SMEM ((RP_LG + 32 * 64) * 4)   // 204800 B

__device__ unsigned char g_flat[NK];
__device__ int           g_bh[SORT_BLOCKS * NEXP];
__device__ int           g_start[NEXP];
__device__ int           g_fix[NTOK];
__device__ int           g_nfix;

__device__ __forceinline__ uint32_t smem_u32(const void* p) {
    uint32_t a;
    asm("{ .reg .u64 t; cvta.to.shared.u64 t, %1; cvt.u32.u64 %0, t; }" : "=r"(a) : "l"(p));
    return a;
}
__device__ __forceinline__ uint32_t tf32_rna(float x) {
    uint32_t r; asm("cvt.rna.tf32.f32 %0, %1;" : "=r"(r) : "f"(x)); return r;
}
__device__ __forceinline__ void cp16(uint32_t dst, const void* src) {
    asm volatile("cp.async.cg.shared.global [%0], [%1], 16;" :: "r"(dst), "l"(src) : "memory");
}
__device__ __forceinline__ void mma_tf32(float* d, const uint32_t* a, const uint32_t* b) {
    asm volatile(
        "mma.sync.aligned.m16n8k8.row.col.f32.tf32.tf32.f32 "
        "{%0,%1,%2,%3}, {%4,%5,%6,%7}, {%8,%9}, {%0,%1,%2,%3};"
        : "+f"(d[0]), "+f"(d[1]), "+f"(d[2]), "+f"(d[3])
        : "r"(a[0]), "r"(a[1]), "r"(a[2]), "r"(a[3]), "r"(b[0]), "r"(b[1]));
}

__device__ __forceinline__ void issue_chunk(uint32_t sbase, int s,
                                            const float* __restrict__ X,
                                            const float* __restrict__ W,
                                            int tok0, int c, int t)
{
    const int r  = t >> 3;
    const int k4 = t & 7;
    const uint32_t stg = sbase + (uint32_t)s * STGB;
    const uint32_t adst = stg + r * (ASTR * 4) + k4 * 16;
    const float* xs = X + (size_t)(tok0 + r) * MDIM + c * KC + k4 * 4;
    #pragma unroll
    for (int i = 0; i < 8; ++i)
        cp16(adst + i * 16 * (ASTR * 4), xs + (size_t)i * 16 * MDIM);
    const uint32_t bdst = stg + (TM + r) * (ASTR * 4) + k4 * 16;
    const float* ws = W + (size_t)r * MDIM + c * KC + k4 * 4;
    #pragma unroll
    for (int i = 0; i < 4; ++i)
        cp16(bdst + i * 16 * (ASTR * 4), ws + (size_t)i * 16 * MDIM);
    asm volatile("cp.async.commit_group;" ::: "memory");
}

__global__ void __launch_bounds__(128, 2)
gate_kernel(const float* __restrict__ X, const float* __restrict__ W,
            float* __restrict__ probs_out, float* __restrict__ cw_out)
{
    extern __shared__ float smf[];
    __shared__ float inv[TM];
    const uint32_t sbase = smem_u32(smf);
    const int t    = threadIdx.x;
    const int wid  = t >> 5;
    const int lane = t & 31;
    const int tok0 = blockIdx.x * TM;

    float acc[2][8][4];
    #pragma unroll
    for (int mt = 0; mt < 2; ++mt)
        #pragma unroll
        for (int nt = 0; nt < 8; ++nt)
            #pragma unroll
            for (int i = 0; i < 4; ++i) acc[mt][nt][i] = 0.f;

    // 3-deep prefetch
    issue_chunk(sbase, 0, X, W, tok0, 0, t);
    issue_chunk(sbase, 1, X, W, tok0, 1, t);
    issue_chunk(sbase, 2, X, W, tok0, 2, t);

    const int ar = lane >> 2;
    const int ac = lane & 3;

    for (int c = 0; c < NCH; ++c) {
        // guarantee chunk c complete: allowed-pending = #issued-after-c
        if (c < NCH - 2)       asm volatile("cp.async.wait_group 2;" ::: "memory");
        else if (c == NCH - 2) asm volatile("cp.async.wait_group 1;" ::: "memory");
        else                   asm volatile("cp.async.wait_group 0;" ::: "memory");
        __syncthreads();
        if (c + 3 < NCH) issue_chunk(sbase, (c + 3) % NSTG, X, W, tok0, c + 3, t);

        const float* Ab = smf + (size_t)(c % NSTG) * STGF;
        const float* Bb = Ab + TM * ASTR;
        #pragma unroll
        for (int ks = 0; ks < 4; ++ks) {
            const int k0 = ks * 8 + ac;
            uint32_t a[2][4], b[8][2];
            #pragma unroll
            for (int mt = 0; mt < 2; ++mt) {
                const float* ap = Ab + (wid * 32 + mt * 16 + ar) * ASTR + k0;
                a[mt][0] = tf32_rna(ap[0]);
                a[mt][1] = tf32_rna(ap[8 * ASTR]);
                a[mt][2] = tf32_rna(ap[4]);
                a[mt][3] = tf32_rna(ap[8 * ASTR + 4]);
            }
            #pragma unroll
            for (int nt = 0; nt < 8; ++nt) {
                const float* bp = Bb + (nt * 8 + ar) * ASTR + k0;
                b[nt][0] = tf32_rna(bp[0]);
                b[nt][1] = tf32_rna(bp[4]);
            }
            #pragma unroll
            for (int mt = 0; mt < 2; ++mt)
                #pragma unroll
                for (int nt = 0; nt < 8; ++nt)
                    mma_tf32(acc[mt][nt], a[mt], b[nt]);
        }
    }
    __syncthreads();                 // all MMA smem reads done -> overlay logits

    float* L = smf;                  // [128][65]
    #pragma unroll
    for (int mt = 0; mt < 2; ++mt) {
        const int r0 = wid * 32 + mt * 16 + ar;
        #pragma unroll
        for (int nt = 0; nt < 8; ++nt) {
            const int n0 = nt * 8 + ac * 2;
            L[r0 * 65 + n0]           = acc[mt][nt][0];
            L[r0 * 65 + n0 + 1]       = acc[mt][nt][1];
            L[(r0 + 8) * 65 + n0]     = acc[mt][nt][2];
            L[(r0 + 8) * 65 + n0 + 1] = acc[mt][nt][3];
        }
    }
    __syncthreads();

    {   // per-token: fast top-3, flag near-ties for exact repair
        float* row = L + t * 65;
        float v1 = -1e30f, v2 = -1e30f, v3 = -1e30f; int i1 = 0, i2 = 0;
        #pragma unroll
        for (int e = 0; e < NEXP; ++e) {
            const float v = row[e];
            if (v > v1)      { v3 = v2; v2 = v1; i2 = i1; v1 = v; i1 = e; }
            else if (v > v2) { v3 = v2; v2 = v;  i2 = e; }
            else if (v > v3) { v3 = v; }
        }
        const int tok = tok0 + t;
        g_flat[(size_t)tok * 2]     = (unsigned char)i1;
        g_flat[(size_t)tok * 2 + 1] = (unsigned char)i2;
        if ((v1 - v2 < TAU) || (v2 - v3 < TAU)) {
            const int j = atomicAdd(&g_nfix, 1);
            if (j < NTOK) g_fix[j] = tok;
        }
        float s = 0.f;
        #pragma unroll
        for (int e = 0; e < NEXP; ++e) {
            const float ex = __expf(row[e] - v1);
            s += ex;
            row[e] = ex;
        }
        inv[t] = 1.0f / s;
    }
    __syncthreads();

    float* pbase = probs_out + (size_t)tok0 * NEXP;
    #pragma unroll
    for (int q = 0; q < (TM * NEXP) / 128; ++q) {
        const int idx = t + q * 128;
        pbase[idx] = L[(idx >> 6) * 65 + (idx & 63)] * inv[idx >> 6];
    }
    cw_out[2 * tok0 + t]       = 1.0f;   // straight-through forward value
    cw_out[2 * tok0 + 128 + t] = 1.0f;
}

// ---------------------------------------------------------------------------
__global__ void reset_kernel() { if (threadIdx.x == 0) g_nfix = 0; }

// Exact (bitwise-reference) recompute of flagged tokens:
//   logit = fl( chain_fp32(k<512) + chain_fp32(k>=512) )
// 2 experts interleaved per thread (4 independent FMA chains) for ILP;
// each expert's chain order is untouched.
__global__ void __launch_bounds__(256)
repair_kernel(const float* __restrict__ X, const float* __restrict__ W)
{
    extern __shared__ float rsm[];
    float* XS = rsm + RP_XS;      // [32][1024]
    float* WS = rsm + RP_WS;      // [16][1024]
    float* LG = rsm + RP_LG;      // [32][64]
    const int t  = threadIdx.x;
    const int ts = t >> 3;        // token slot 0..31
    const int el = t & 7;         // expert lane in group

    const int nf = g_nfix;
    for (int base = blockIdx.x * FIX_PER_BLK; base < nf; base += gridDim.x * FIX_PER_BLK) {
        const int nt = min(FIX_PER_BLK, nf - base);
        __syncthreads();
        // load X rows of flagged tokens
        for (int i = 0; i < 32; ++i) {
            const int idx = t + i * 256;          // 8192 float4 slots
            const int row = idx >> 8, c4 = idx & 255;
            if (row < nt) {
                const int tok = g_fix[base + row];
                *(float4*)(XS + row * 1024 + c4 * 4) =
                    *(const float4*)(X + (size_t)tok * MDIM + c4 * 4);
            }
        }
        for (int eg = 0; eg < 4; ++eg) {
            __syncthreads();
            // load W rows eg*16 .. eg*16+15
            #pragma unroll
            for (int i = 0; i < 16; ++i) {
                const int idx = t + i * 256;      // 4096 float4 slots
                const int row = idx >> 8, c4 = idx & 255;
                *(float4*)(WS + row * 1024 + c4 * 4) =
                    *(const float4*)(W + (size_t)(eg * 16 + row) * MDIM + c4 * 4);
            }
            __syncthreads();
            if (ts < nt) {
                const float* xr  = XS + ts * 1024;
                const float* wr0 = WS + el * 1024;          // expert eg*16+el
                const float* wr1 = WS + (el + 8) * 1024;    // expert eg*16+el+8
                float a0 = 0.f, a1 = 0.f, b0 = 0.f, b1 = 0.f;
                for (int k = 0; k < 512; k += 4) {
                    const float4 x0 = *(const float4*)(xr + k);
                    const float4 x1 = *(const float4*)(xr + 512 + k);
                    const float4 wa0 = *(const float4*)(wr0 + k);
                    const float4 wa1 = *(const float4*)(wr0 + 512 + k);
                    const float4 wb0 = *(const float4*)(wr1 + k);
                    const float4 wb1 = *(const float4*)(wr1 + 512 + k);
                    a0 = fmaf(x0.x, wa0.x, a0); a1 = fmaf(x1.x, wa1.x, a1);
                    b0 = fmaf(x0.x, wb0.x, b0); b1 = fmaf(x1.x, wb1.x, b1);
                    a0 = fmaf(x0.y, wa0.y, a0); a1 = fmaf(x1.y, wa1.y, a1);
                    b0 = fmaf(x0.y, wb0.y, b0); b1 = fmaf(x1.y, wb1.y, b1);
                    a0 = fmaf(x0.z, wa0.z, a0); a1 = fmaf(x1.z, wa1.z, a1);
                    b0 = fmaf(x0.z, wb0.z, b0); b1 = fmaf(x1.z, wb1.z, b1);
                    a0 = fmaf(x0.w, wa0.w, a0); a1 = fmaf(x1.w, wa1.w, a1);
                    b0 = fmaf(x0.w, wb0.w, b0); b1 = fmaf(x1.w, wb1.w, b1);
                }
                LG[ts * 64 + eg * 16 + el]     = a0 + a1;
                LG[ts * 64 + eg * 16 + el + 8] = b0 + b1;
            }
        }
        __syncthreads();
        if (t < nt) {
            const float* row = LG + t * 64;
            float v1 = -1e30f, v2 = -1e30f; int i1 = 0, i2 = 0;
            #pragma unroll
            for (int e = 0; e < NEXP; ++e) {
                const float v = row[e];
                if (v > v1)      { v2 = v1; i2 = i1; v1 = v; i1 = e; }
                else if (v > v2) { v2 = v;  i2 = e; }
            }
            const int tok = g_fix[base + t];
            g_flat[(size_t)tok * 2]     = (unsigned char)i1;
            g_flat[(size_t)tok * 2 + 1] = (unsigned char)i2;
        }
    }
}

// ---------------------------------------------------------------------------
// Counting sort (post-repair): hist -> scan -> rank
// ---------------------------------------------------------------------------
__global__ void hist_kernel()
{
    __shared__ int h[NEXP];
    const int t = threadIdx.x;       // 256 threads
    if (t < NEXP) h[t] = 0;
    __syncthreads();
    const int base = blockIdx.x * SORT_CHUNK;
    #pragma unroll
    for (int q = 0; q < SORT_CHUNK / 256; ++q)
        atomicAdd(&h[g_flat[base + t + q * 256]], 1);
    __syncthreads();
    if (t < NEXP) g_bh[blockIdx.x * NEXP + t] = h[t];
}

// 1 block, 1024 threads: warp w scans experts 2w, 2w+1 across 512 chunks
__global__ void scan_kernel(float* __restrict__ splits_out)
{
    __shared__ int tot[NEXP];
    const int w    = threadIdx.x >> 5;
    const int lane = threadIdx.x & 31;
    #pragma unroll
    for (int ee = 0; ee < 2; ++ee) {
        const int e = w * 2 + ee;
        int v[16], s = 0;
        #pragma unroll
        for (int i = 0; i < 16; ++i) v[i] = g_bh[(lane * 16 + i) * NEXP + e];
        #pragma unroll
        for (int i = 0; i < 16; ++i) { const int x = v[i]; v[i] = s; s += x; }
        int run = s;
        #pragma unroll
        for (int off = 1; off < 32; off <<= 1) {
            const int n = __shfl_up_sync(0xffffffffu, run, off);
            if (lane >= off) run += n;
        }
        const int excl = run - s;
        #pragma unroll
        for (int i = 0; i < 16; ++i) g_bh[(lane * 16 + i) * NEXP + e] = v[i] + excl;
        if (lane == 31) tot[e] = run;
    }
    __syncthreads();
    if (threadIdx.x < NEXP) splits_out[threadIdx.x] = (float)tot[threadIdx.x];
    if (threadIdx.x == 0) {
        int base = 0;
        for (int e = 0; e < NEXP; ++e) { g_start[e] = base; base += tot[e]; }
    }
}

__global__ void rank_kernel(float* __restrict__ to_out, float* __restrict__ ro_out)
{
    __shared__ int cnt[NEXP];
    const int lane = threadIdx.x;
    cnt[lane]      = g_start[lane]      + g_bh[blockIdx.x * NEXP + lane];
    cnt[lane + 32] = g_start[lane + 32] + g_bh[blockIdx.x * NEXP + lane + 32];
    __syncwarp();
    const int base = blockIdx.x * SORT_CHUNK;
    #pragma unroll
    for (int it = 0; it < SORT_CHUNK / 32; ++it) {
        const int i = base + it * 32 + lane;
        const int e = g_flat[i];
        const unsigned peers = __match_any_sync(0xffffffffu, e);
        const int leader = __ffs(peers) - 1;
        const int prior  = __popc(peers & ((1u << lane) - 1));
        int b = 0;
        if (lane == leader) b = atomicAdd(&cnt[e], __popc(peers));
        b = __shfl_sync(peers, b, leader);
        const int p = b + prior;
        to_out[p] = (float)(i >> 1);
        ro_out[i] = (float)p;
    }
}

// ---------------------------------------------------------------------------
extern "C" void kernel_launch(void* const* d_in, const int* in_sizes, int n_in,
                              void* d_out, int out_size)
{
    const float* X = (const float*)d_in[0];   // [131072, 1024]
    const float* W = (const float*)d_in[1];   // [64, 1024]
    float* out = (float*)d_out;

    float* TO  = out;
    float* RO  = out + NK;
    float* CW  = out + 2 * NK;
    float* SPL = out + 3 * NK;
    float* PR  = out + 3 * NK + NEXP;

    cudaFuncSetAttribute(gate_kernel, cudaFuncAttributeMaxDynamicSharedMemorySize, GK_SMEM);
    cudaFuncSetAttribute(repair_kernel, cudaFuncAttributeMaxDynamicSharedMemorySize, RP_SMEM);

    reset_kernel<<<1, 32>>>();
    gate_kernel<<<NTOK / TM, 128, GK_SMEM>>>(X, W, PR, CW);
    repair_kernel<<<REPAIR_BLOCKS, 256, RP_SMEM>>>(X, W);
    hist_kernel<<<SORT_BLOCKS, 256>>>();
    scan_kernel<<<1, 1024>>>(SPL);
    rank_kernel<<<SORT_BLOCKS, 32>>>(TO, RO);
}

// round 10
// speedup vs baseline: 1.8469x; 1.0058x over previous
#include <cuda_runtime.h>
#include <cstdint>

// ---------------------------------------------------------------------------
// LocalGate: N=131072 tokens, D=1024, E=64, K=2, GATE_ST.
// Strategy:
//   1) gate: tf32 mma.sync GEMM (RNA operands; W pre-converted) -> probs,
//      fast top-3; flag near-tie tokens (gap < TAU). 3-deep cp.async pipeline,
//      3 CTAs/SM (12 warps) via 60KB smem.
//   2) repair: recompute flagged tokens' logits EXACTLY (Eigen two-panel fp32
//      chain, bitwise = reference) and overwrite their top-2.
//   3) counting sort (hist/scan/rank) on repaired assignments.
// ---------------------------------------------------------------------------

#define NTOK  131072
#define MDIM  1024
#define NEXP  64
#define NK    (NTOK * 2)
#define TM    128
#define KC    16
#define NCH   (MDIM / KC)           // 64
#define ASTR  20                    // row stride floats (16 + 4 pad; (ar*20+ac)%32 distinct)
#define STGF  ((TM + NEXP) * ASTR)  // 3840 floats
#define STGB  (STGF * 4)            // 15360 B
#define NSTG  4
#define GK_SMEM (NSTG * STGB)       // 61440 -> 3 CTAs/SM

#define TAU   2.5e-3f

#define SORT_BLOCKS 512
#define SORT_CHUNK  (NK / SORT_BLOCKS)  // 512

#define FIX_PER_BLK 32
#define REPAIR_BLOCKS 128
#define RP_XS   0
#define RP_WS   (32 * 1024)
#define RP_LG   (RP_WS + 16 * 1024)
#define RP_SMEM ((RP_LG + 32 * 64) * 4)   // 204800 B

__device__ unsigned char g_flat[NK];
__device__ int           g_bh[SORT_BLOCKS * NEXP];
__device__ int           g_start[NEXP];
__device__ int           g_fix[NTOK];
__device__ int           g_nfix;
__device__ uint32_t      g_wtf32[NEXP * MDIM];   // W pre-rounded to tf32 (RNA)

__device__ __forceinline__ uint32_t smem_u32(const void* p) {
    uint32_t a;
    asm("{ .reg .u64 t; cvta.to.shared.u64 t, %1; cvt.u32.u64 %0, t; }" : "=r"(a) : "l"(p));
    return a;
}
__device__ __forceinline__ uint32_t tf32_rna(float x) {
    uint32_t r; asm("cvt.rna.tf32.f32 %0, %1;" : "=r"(r) : "f"(x)); return r;
}
__device__ __forceinline__ void cp16(uint32_t dst, const void* src) {
    asm volatile("cp.async.cg.shared.global [%0], [%1], 16;" :: "r"(dst), "l"(src) : "memory");
}
__device__ __forceinline__ void mma_tf32(float* d, const uint32_t* a, const uint32_t* b) {
    asm volatile(
        "mma.sync.aligned.m16n8k8.row.col.f32.tf32.tf32.f32 "
        "{%0,%1,%2,%3}, {%4,%5,%6,%7}, {%8,%9}, {%0,%1,%2,%3};"
        : "+f"(d[0]), "+f"(d[1]), "+f"(d[2]), "+f"(d[3])
        : "r"(a[0]), "r"(a[1]), "r"(a[2]), "r"(a[3]), "r"(b[0]), "r"(b[1]));
}

// one K-chunk (A:128x16 floats, B:64x16 tf32-bits) into stage s
__device__ __forceinline__ void issue_chunk(uint32_t sbase, int s,
                                            const float* __restrict__ X,
                                            int tok0, int c, int t)
{
    const int r  = t >> 2;          // 0..31
    const int k4 = t & 3;           // 0..3
    const uint32_t stg = sbase + (uint32_t)s * STGB;
    const float* xs = X + (size_t)(tok0 + r) * MDIM + c * KC + k4 * 4;
    const uint32_t adst = stg + r * (ASTR * 4) + k4 * 16;
    #pragma unroll
    for (int i = 0; i < 4; ++i)
        cp16(adst + i * 32 * (ASTR * 4), xs + (size_t)i * 32 * MDIM);
    const uint32_t* ws = g_wtf32 + (size_t)r * MDIM + c * KC + k4 * 4;
    const uint32_t bdst = stg + (TM + r) * (ASTR * 4) + k4 * 16;
    #pragma unroll
    for (int i = 0; i < 2; ++i)
        cp16(bdst + i * 32 * (ASTR * 4), ws + (size_t)i * 32 * MDIM);
    asm volatile("cp.async.commit_group;" ::: "memory");
}

__global__ void __launch_bounds__(128, 3)
gate_kernel(const float* __restrict__ X,
            float* __restrict__ probs_out, float* __restrict__ cw_out)
{
    extern __shared__ float smf[];
    __shared__ float inv[TM];
    const uint32_t sbase = smem_u32(smf);
    const int t    = threadIdx.x;
    const int wid  = t >> 5;
    const int lane = t & 31;
    const int tok0 = blockIdx.x * TM;

    float acc[2][8][4];
    #pragma unroll
    for (int mt = 0; mt < 2; ++mt)
        #pragma unroll
        for (int nt = 0; nt < 8; ++nt)
            #pragma unroll
            for (int i = 0; i < 4; ++i) acc[mt][nt][i] = 0.f;

    issue_chunk(sbase, 0, X, tok0, 0, t);
    issue_chunk(sbase, 1, X, tok0, 1, t);
    issue_chunk(sbase, 2, X, tok0, 2, t);

    const int ar = lane >> 2;
    const int ac = lane & 3;

    for (int c = 0; c < NCH; ++c) {
        if (c < NCH - 2)       asm volatile("cp.async.wait_group 2;" ::: "memory");
        else if (c == NCH - 2) asm volatile("cp.async.wait_group 1;" ::: "memory");
        else                   asm volatile("cp.async.wait_group 0;" ::: "memory");
        __syncthreads();
        if (c + 3 < NCH) issue_chunk(sbase, (c + 3) & 3, X, tok0, c + 3, t);

        const float*    Ab = smf + (size_t)(c & 3) * STGF;
        const uint32_t* Bb = reinterpret_cast<const uint32_t*>(Ab + TM * ASTR);
        #pragma unroll
        for (int ks = 0; ks < 2; ++ks) {            // ascending K
            const int k0 = ks * 8 + ac;
            uint32_t a[2][4], b[8][2];
            #pragma unroll
            for (int mt = 0; mt < 2; ++mt) {
                const float* ap = Ab + (wid * 32 + mt * 16 + ar) * ASTR + k0;
                a[mt][0] = tf32_rna(ap[0]);
                a[mt][1] = tf32_rna(ap[8 * ASTR]);
                a[mt][2] = tf32_rna(ap[4]);
                a[mt][3] = tf32_rna(ap[8 * ASTR + 4]);
            }
            #pragma unroll
            for (int nt = 0; nt < 8; ++nt) {        // pre-converted: no CVT
                const uint32_t* bp = Bb + (nt * 8 + ar) * ASTR + k0;
                b[nt][0] = bp[0];
                b[nt][1] = bp[4];
            }
            #pragma unroll
            for (int mt = 0; mt < 2; ++mt)
                #pragma unroll
                for (int nt = 0; nt < 8; ++nt)
                    mma_tf32(acc[mt][nt], a[mt], b[nt]);
        }
    }
    __syncthreads();                 // all MMA smem reads done -> overlay logits

    float* L = smf;                  // [128][65] = 8320 floats < 15360 avail
    #pragma unroll
    for (int mt = 0; mt < 2; ++mt) {
        const int r0 = wid * 32 + mt * 16 + ar;
        #pragma unroll
        for (int nt = 0; nt < 8; ++nt) {
            const int n0 = nt * 8 + ac * 2;
            L[r0 * 65 + n0]           = acc[mt][nt][0];
            L[r0 * 65 + n0 + 1]       = acc[mt][nt][1];
            L[(r0 + 8) * 65 + n0]     = acc[mt][nt][2];
            L[(r0 + 8) * 65 + n0 + 1] = acc[mt][nt][3];
        }
    }
    __syncthreads();

    {   // per-token: fast top-3, flag near-ties for exact repair
        float* row = L + t * 65;
        float v1 = -1e30f, v2 = -1e30f, v3 = -1e30f; int i1 = 0, i2 = 0;
        #pragma unroll
        for (int e = 0; e < NEXP; ++e) {
            const float v = row[e];
            if (v > v1)      { v3 = v2; v2 = v1; i2 = i1; v1 = v; i1 = e; }
            else if (v > v2) { v3 = v2; v2 = v;  i2 = e; }
            else if (v > v3) { v3 = v; }
        }
        const int tok = tok0 + t;
        g_flat[(size_t)tok * 2]     = (unsigned char)i1;
        g_flat[(size_t)tok * 2 + 1] = (unsigned char)i2;
        if ((v1 - v2 < TAU) || (v2 - v3 < TAU)) {
            const int j = atomicAdd(&g_nfix, 1);
            if (j < NTOK) g_fix[j] = tok;
        }
        float s = 0.f;
        #pragma unroll
        for (int e = 0; e < NEXP; ++e) {
            const float ex = __expf(row[e] - v1);
            s += ex;
            row[e] = ex;
        }
        inv[t] = 1.0f / s;
    }
    __syncthreads();

    float* pbase = probs_out + (size_t)tok0 * NEXP;
    #pragma unroll
    for (int q = 0; q < (TM * NEXP) / 128; ++q) {
        const int idx = t + q * 128;
        pbase[idx] = L[(idx >> 6) * 65 + (idx & 63)] * inv[idx >> 6];
    }
    cw_out[2 * tok0 + t]       = 1.0f;   // straight-through forward value
    cw_out[2 * tok0 + 128 + t] = 1.0f;
}

// ---------------------------------------------------------------------------
__global__ void wconv_kernel(const float* __restrict__ W)
{
    const int i = blockIdx.x * 256 + threadIdx.x;   // 65536 total
    g_wtf32[i] = tf32_rna(W[i]);
    if (i == 0) g_nfix = 0;
}

// Exact (bitwise-reference) recompute of flagged tokens:
//   logit = fl( chain_fp32(k<512) + chain_fp32(k>=512) )
__global__ void __launch_bounds__(256)
repair_kernel(const float* __restrict__ X, const float* __restrict__ W)
{
    extern __shared__ float rsm[];
    float* XS = rsm + RP_XS;      // [32][1024]
    float* WS = rsm + RP_WS;      // [16][1024]
    float* LG = rsm + RP_LG;      // [32][64]
    const int t  = threadIdx.x;
    const int ts = t >> 3;
    const int el = t & 7;

    const int nf = g_nfix;
    for (int base = blockIdx.x * FIX_PER_BLK; base < nf; base += gridDim.x * FIX_PER_BLK) {
        const int nt = min(FIX_PER_BLK, nf - base);
        __syncthreads();
        for (int i = 0; i < 32; ++i) {
            const int idx = t + i * 256;
            const int row = idx >> 8, c4 = idx & 255;
            if (row < nt) {
                const int tok = g_fix[base + row];
                *(float4*)(XS + row * 1024 + c4 * 4) =
                    *(const float4*)(X + (size_t)tok * MDIM + c4 * 4);
            }
        }
        for (int eg = 0; eg < 4; ++eg) {
            __syncthreads();
            #pragma unroll
            for (int i = 0; i < 16; ++i) {
                const int idx = t + i * 256;
                const int row = idx >> 8, c4 = idx & 255;
                *(float4*)(WS + row * 1024 + c4 * 4) =
                    *(const float4*)(W + (size_t)(eg * 16 + row) * MDIM + c4 * 4);
            }
            __syncthreads();
            if (ts < nt) {
                const float* xr  = XS + ts * 1024;
                const float* wr0 = WS + el * 1024;
                const float* wr1 = WS + (el + 8) * 1024;
                float a0 = 0.f, a1 = 0.f, b0 = 0.f, b1 = 0.f;
                for (int k = 0; k < 512; k += 4) {
                    const float4 x0 = *(const float4*)(xr + k);
                    const float4 x1 = *(const float4*)(xr + 512 + k);
                    const float4 wa0 = *(const float4*)(wr0 + k);
                    const float4 wa1 = *(const float4*)(wr0 + 512 + k);
                    const float4 wb0 = *(const float4*)(wr1 + k);
                    const float4 wb1 = *(const float4*)(wr1 + 512 + k);
                    a0 = fmaf(x0.x, wa0.x, a0); a1 = fmaf(x1.x, wa1.x, a1);
                    b0 = fmaf(x0.x, wb0.x, b0); b1 = fmaf(x1.x, wb1.x, b1);
                    a0 = fmaf(x0.y, wa0.y, a0); a1 = fmaf(x1.y, wa1.y, a1);
                    b0 = fmaf(x0.y, wb0.y, b0); b1 = fmaf(x1.y, wb1.y, b1);
                    a0 = fmaf(x0.z, wa0.z, a0); a1 = fmaf(x1.z, wa1.z, a1);
                    b0 = fmaf(x0.z, wb0.z, b0); b1 = fmaf(x1.z, wb1.z, b1);
                    a0 = fmaf(x0.w, wa0.w, a0); a1 = fmaf(x1.w, wa1.w, a1);
                    b0 = fmaf(x0.w, wb0.w, b0); b1 = fmaf(x1.w, wb1.w, b1);
                }
                LG[ts * 64 + eg * 16 + el]     = a0 + a1;
                LG[ts * 64 + eg * 16 + el + 8] = b0 + b1;
            }
        }
        __syncthreads();
        if (t < nt) {
            const float* row = LG + t * 64;
            float v1 = -1e30f, v2 = -1e30f; int i1 = 0, i2 = 0;
            #pragma unroll
            for (int e = 0; e < NEXP; ++e) {
                const float v = row[e];
                if (v > v1)      { v2 = v1; i2 = i1; v1 = v; i1 = e; }
                else if (v > v2) { v2 = v;  i2 = e; }
            }
            const int tok = g_fix[base + t];
            g_flat[(size_t)tok * 2]     = (unsigned char)i1;
            g_flat[(size_t)tok * 2 + 1] = (unsigned char)i2;
        }
    }
}

// ---------------------------------------------------------------------------
// Counting sort (post-repair): hist -> scan -> rank
// ---------------------------------------------------------------------------
__global__ void hist_kernel()
{
    __shared__ int h[NEXP];
    const int t = threadIdx.x;
    if (t < NEXP) h[t] = 0;
    __syncthreads();
    const int base = blockIdx.x * SORT_CHUNK;
    #pragma unroll
    for (int q = 0; q < SORT_CHUNK / 256; ++q)
        atomicAdd(&h[g_flat[base + t + q * 256]], 1);
    __syncthreads();
    if (t < NEXP) g_bh[blockIdx.x * NEXP + t] = h[t];
}

__global__ void scan_kernel(float* __restrict__ splits_out)
{
    __shared__ int tot[NEXP];
    const int w    = threadIdx.x >> 5;
    const int lane = threadIdx.x & 31;
    #pragma unroll
    for (int ee = 0; ee < 2; ++ee) {
        const int e = w * 2 + ee;
        int v[16], s = 0;
        #pragma unroll
        for (int i = 0; i < 16; ++i) v[i] = g_bh[(lane * 16 + i) * NEXP + e];
        #pragma unroll
        for (int i = 0; i < 16; ++i) { const int x = v[i]; v[i] = s; s += x; }
        int run = s;
        #pragma unroll
        for (int off = 1; off < 32; off <<= 1) {
            const int n = __shfl_up_sync(0xffffffffu, run, off);
            if (lane >= off) run += n;
        }
        const int excl = run - s;
        #pragma unroll
        for (int i = 0; i < 16; ++i) g_bh[(lane * 16 + i) * NEXP + e] = v[i] + excl;
        if (lane == 31) tot[e] = run;
    }
    __syncthreads();
    if (threadIdx.x < NEXP) splits_out[threadIdx.x] = (float)tot[threadIdx.x];
    if (threadIdx.x == 0) {
        int base = 0;
        for (int e = 0; e < NEXP; ++e) { g_start[e] = base; base += tot[e]; }
    }
}

__global__ void rank_kernel(float* __restrict__ to_out, float* __restrict__ ro_out)
{
    __shared__ int cnt[NEXP];
    const int lane = threadIdx.x;
    cnt[lane]      = g_start[lane]      + g_bh[blockIdx.x * NEXP + lane];
    cnt[lane + 32] = g_start[lane + 32] + g_bh[blockIdx.x * NEXP + lane + 32];
    __syncwarp();
    const int base = blockIdx.x * SORT_CHUNK;
    #pragma unroll
    for (int it = 0; it < SORT_CHUNK / 32; ++it) {
        const int i = base + it * 32 + lane;
        const int e = g_flat[i];
        const unsigned peers = __match_any_sync(0xffffffffu, e);
        const int leader = __ffs(peers) - 1;
        const int prior  = __popc(peers & ((1u << lane) - 1));
        int b = 0;
        if (lane == leader) b = atomicAdd(&cnt[e], __popc(peers));
        b = __shfl_sync(peers, b, leader);
        const int p = b + prior;
        to_out[p] = (float)(i >> 1);
        ro_out[i] = (float)p;
    }
}

// ---------------------------------------------------------------------------
extern "C" void kernel_launch(void* const* d_in, const int* in_sizes, int n_in,
                              void* d_out, int out_size)
{
    const float* X = (const float*)d_in[0];   // [131072, 1024]
    const float* W = (const float*)d_in[1];   // [64, 1024]
    float* out = (float*)d_out;

    float* TO  = out;
    float* RO  = out + NK;
    float* CW  = out + 2 * NK;
    float* SPL = out + 3 * NK;
    float* PR  = out + 3 * NK + NEXP;

    cudaFuncSetAttribute(gate_kernel, cudaFuncAttributeMaxDynamicSharedMemorySize, GK_SMEM);
    cudaFuncSetAttribute(repair_kernel, cudaFuncAttributeMaxDynamicSharedMemorySize, RP_SMEM);

    wconv_kernel<<<256, 256>>>(W);
    gate_kernel<<<NTOK / TM, 128, GK_SMEM>>>(X, PR, CW);
    repair_kernel<<<REPAIR_BLOCKS, 256, RP_SMEM>>>(X, W);
    hist_kernel<<<SORT_BLOCKS, 256>>>();
    scan_kernel<<<1, 1024>>>(SPL);
    rank_kernel<<<SORT_BLOCKS, 32>>>(TO, RO);
}

// round 11
// speedup vs baseline: 1.9661x; 1.0645x over previous
#include <cuda_runtime.h>
#include <cstdint>

// ---------------------------------------------------------------------------
// LocalGate: N=131072 tokens, D=1024, E=64, K=2, GATE_ST.
// Strategy:
//   1) gate: fp16 m16n8k16 mma.sync GEMM (fp32 accum; fp16 sig == tf32 sig)
//      -> probs (~3e-4 < 1e-3), fast top-3; flag near-tie tokens (gap < TAU).
//      HMMA instruction count HALVED vs tf32 m16n8k8 (rate-bound pipe).
//   2) repair: recompute flagged tokens' logits EXACTLY (Eigen two-panel fp32
//      chain, bitwise = reference) and overwrite their top-2.
//   3) counting sort (hist/scan/rank) on repaired assignments.
// ---------------------------------------------------------------------------

#define NTOK  131072
#define MDIM  1024
#define NEXP  64
#define NK    (NTOK * 2)
#define TM    128
#define KC    16
#define NCH   (MDIM / KC)           // 64
#define ASTR  24                    // A row stride in floats (16 + 8 pad; LDS.64 conflict-free)
#define BSTR  12                    // B row stride in words (8 data + 4 pad; LDS.32 conflict-free)
#define ABYT  (TM * ASTR * 4)       // 12288
#define BBYT  (NEXP * BSTR * 4)     // 3072
#define STGB  (ABYT + BBYT)         // 15360
#define STGF  (STGB / 4)            // 3840 floats
#define NSTG  4
#define GK_SMEM (NSTG * STGB)       // 61440 -> 3 CTAs/SM

#define TAU   3.0e-3f

#define SORT_BLOCKS 512
#define SORT_CHUNK  (NK / SORT_BLOCKS)  // 512

#define FIX_PER_BLK 32
#define REPAIR_BLOCKS 128
#define RP_XS   0
#define RP_WS   (32 * 1024)
#define RP_LG   (RP_WS + 16 * 1024)
#define RP_SMEM ((RP_LG + 32 * 64) * 4)   // 204800 B

__device__ unsigned char g_flat[NK];
__device__ int           g_bh[SORT_BLOCKS * NEXP];
__device__ int           g_start[NEXP];
__device__ int           g_fix[NTOK];
__device__ int           g_nfix;
__device__ uint32_t      g_whalf[NEXP * MDIM / 2];   // W as packed f16x2 (k-major)

__device__ __forceinline__ uint32_t smem_u32(const void* p) {
    uint32_t a;
    asm("{ .reg .u64 t; cvta.to.shared.u64 t, %1; cvt.u32.u64 %0, t; }" : "=r"(a) : "l"(p));
    return a;
}
// pack {lo = f16(x0), hi = f16(x1)}  (PTX: first source -> upper half)
__device__ __forceinline__ uint32_t f16x2_rn(float x0, float x1) {
    uint32_t r; asm("cvt.rn.f16x2.f32 %0, %1, %2;" : "=r"(r) : "f"(x1), "f"(x0)); return r;
}
__device__ __forceinline__ void cp16(uint32_t dst, const void* src) {
    asm volatile("cp.async.cg.shared.global [%0], [%1], 16;" :: "r"(dst), "l"(src) : "memory");
}
__device__ __forceinline__ void mma_f16(float* d, const uint32_t* a, const uint32_t* b) {
    asm volatile(
        "mma.sync.aligned.m16n8k16.row.col.f32.f16.f16.f32 "
        "{%0,%1,%2,%3}, {%4,%5,%6,%7}, {%8,%9}, {%0,%1,%2,%3};"
        : "+f"(d[0]), "+f"(d[1]), "+f"(d[2]), "+f"(d[3])
        : "r"(a[0]), "r"(a[1]), "r"(a[2]), "r"(a[3]), "r"(b[0]), "r"(b[1]));
}

// one K-chunk (A:128x16 fp32, B:64x16 fp16) into stage s
__device__ __forceinline__ void issue_chunk(uint32_t sbase, int s,
                                            const float* __restrict__ X,
                                            int tok0, int c, int t)
{
    const uint32_t stg = sbase + (uint32_t)s * STGB;
    {   // A: 32 rows x 4 iters, 64B contiguous per row (4 threads x 16B)
        const int r  = t >> 2;
        const int k4 = t & 3;
        const float* xs = X + (size_t)(tok0 + r) * MDIM + c * KC + k4 * 4;
        const uint32_t adst = stg + r * (ASTR * 4) + k4 * 16;
        #pragma unroll
        for (int i = 0; i < 4; ++i)
            cp16(adst + i * 32 * (ASTR * 4), xs + (size_t)i * 32 * MDIM);
    }
    {   // B: 64 rows x 32B (2 threads x 16B per row)
        const int r = t >> 1;
        const int h = t & 1;
        const uint32_t* ws = g_whalf + (size_t)r * (MDIM / 2) + c * 8 + h * 4;
        cp16(stg + ABYT + r * (BSTR * 4) + h * 16, ws);
    }
    asm volatile("cp.async.commit_group;" ::: "memory");
}

__global__ void __launch_bounds__(128, 3)
gate_kernel(const float* __restrict__ X,
            float* __restrict__ probs_out, float* __restrict__ cw_out)
{
    extern __shared__ float smf[];
    __shared__ float inv[TM];
    const uint32_t sbase = smem_u32(smf);
    const int t    = threadIdx.x;
    const int wid  = t >> 5;
    const int lane = t & 31;
    const int tok0 = blockIdx.x * TM;

    float acc[2][8][4];
    #pragma unroll
    for (int mt = 0; mt < 2; ++mt)
        #pragma unroll
        for (int nt = 0; nt < 8; ++nt)
            #pragma unroll
            for (int i = 0; i < 4; ++i) acc[mt][nt][i] = 0.f;

    issue_chunk(sbase, 0, X, tok0, 0, t);
    issue_chunk(sbase, 1, X, tok0, 1, t);
    issue_chunk(sbase, 2, X, tok0, 2, t);

    const int gr = lane >> 2;     // 0..7
    const int ac = lane & 3;      // 0..3

    for (int c = 0; c < NCH; ++c) {
        if (c < NCH - 2)       asm volatile("cp.async.wait_group 2;" ::: "memory");
        else if (c == NCH - 2) asm volatile("cp.async.wait_group 1;" ::: "memory");
        else                   asm volatile("cp.async.wait_group 0;" ::: "memory");
        __syncthreads();
        if (c + 3 < NCH) issue_chunk(sbase, (c + 3) & 3, X, tok0, c + 3, t);

        const float*    Ab = smf + (size_t)(c & 3) * STGF;
        const uint32_t* Bw = reinterpret_cast<const uint32_t*>(Ab + TM * ASTR);

        // one m16n8k16 step covers the whole 16-k chunk
        uint32_t a[2][4], b[8][2];
        #pragma unroll
        for (int mt = 0; mt < 2; ++mt) {
            const int r0 = wid * 32 + mt * 16 + gr;
            const float2 x0 = *(const float2*)(Ab + r0 * ASTR + 2 * ac);            // k 2ac..2ac+1
            const float2 x1 = *(const float2*)(Ab + (r0 + 8) * ASTR + 2 * ac);
            const float2 x2 = *(const float2*)(Ab + r0 * ASTR + 2 * ac + 8);        // k 2ac+8..9
            const float2 x3 = *(const float2*)(Ab + (r0 + 8) * ASTR + 2 * ac + 8);
            a[mt][0] = f16x2_rn(x0.x, x0.y);
            a[mt][1] = f16x2_rn(x1.x, x1.y);
            a[mt][2] = f16x2_rn(x2.x, x2.y);
            a[mt][3] = f16x2_rn(x3.x, x3.y);
        }
        #pragma unroll
        for (int nt = 0; nt < 8; ++nt) {
            const uint32_t* bp = Bw + (nt * 8 + gr) * BSTR + ac;
            b[nt][0] = bp[0];     // k halves 2ac..2ac+1
            b[nt][1] = bp[4];     // k halves 2ac+8..2ac+9
        }
        #pragma unroll
        for (int mt = 0; mt < 2; ++mt)
            #pragma unroll
            for (int nt = 0; nt < 8; ++nt)
                mma_f16(acc[mt][nt], a[mt], b[nt]);
    }
    __syncthreads();                 // all MMA smem reads done -> overlay logits

    float* L = smf;                  // [128][65] = 8320 floats
    #pragma unroll
    for (int mt = 0; mt < 2; ++mt) {
        const int r0 = wid * 32 + mt * 16 + gr;
        #pragma unroll
        for (int nt = 0; nt < 8; ++nt) {
            const int n0 = nt * 8 + ac * 2;
            L[r0 * 65 + n0]           = acc[mt][nt][0];
            L[r0 * 65 + n0 + 1]       = acc[mt][nt][1];
            L[(r0 + 8) * 65 + n0]     = acc[mt][nt][2];
            L[(r0 + 8) * 65 + n0 + 1] = acc[mt][nt][3];
        }
    }
    __syncthreads();

    {   // per-token: fast top-3, flag near-ties for exact repair
        float* row = L + t * 65;
        float v1 = -1e30f, v2 = -1e30f, v3 = -1e30f; int i1 = 0, i2 = 0;
        #pragma unroll
        for (int e = 0; e < NEXP; ++e) {
            const float v = row[e];
            if (v > v1)      { v3 = v2; v2 = v1; i2 = i1; v1 = v; i1 = e; }
            else if (v > v2) { v3 = v2; v2 = v;  i2 = e; }
            else if (v > v3) { v3 = v; }
        }
        const int tok = tok0 + t;
        g_flat[(size_t)tok * 2]     = (unsigned char)i1;
        g_flat[(size_t)tok * 2 + 1] = (unsigned char)i2;
        if ((v1 - v2 < TAU) || (v2 - v3 < TAU)) {
            const int j = atomicAdd(&g_nfix, 1);
            if (j < NTOK) g_fix[j] = tok;
        }
        float s = 0.f;
        #pragma unroll
        for (int e = 0; e < NEXP; ++e) {
            const float ex = __expf(row[e] - v1);
            s += ex;
            row[e] = ex;
        }
        inv[t] = 1.0f / s;
    }
    __syncthreads();

    float* pbase = probs_out + (size_t)tok0 * NEXP;
    #pragma unroll
    for (int q = 0; q < (TM * NEXP) / 128; ++q) {
        const int idx = t + q * 128;
        pbase[idx] = L[(idx >> 6) * 65 + (idx & 63)] * inv[idx >> 6];
    }
    cw_out[2 * tok0 + t]       = 1.0f;   // straight-through forward value
    cw_out[2 * tok0 + 128 + t] = 1.0f;
}

// ---------------------------------------------------------------------------
__global__ void wconv_kernel(const float* __restrict__ W)
{
    const int i = blockIdx.x * 256 + threadIdx.x;   // 32768 packed words
    g_whalf[i] = f16x2_rn(W[2 * i], W[2 * i + 1]);
    if (i == 0) g_nfix = 0;
}

// Exact (bitwise-reference) recompute of flagged tokens:
//   logit = fl( chain_fp32(k<512) + chain_fp32(k>=512) )
__global__ void __launch_bounds__(256)
repair_kernel(const float* __restrict__ X, const float* __restrict__ W)
{
    extern __shared__ float rsm[];
    float* XS = rsm + RP_XS;      // [32][1024]
    float* WS = rsm + RP_WS;      // [16][1024]
    float* LG = rsm + RP_LG;      // [32][64]
    const int t  = threadIdx.x;
    const int ts = t >> 3;
    const int el = t & 7;

    const int nf = g_nfix;
    for (int base = blockIdx.x * FIX_PER_BLK; base < nf; base += gridDim.x * FIX_PER_BLK) {
        const int nt = min(FIX_PER_BLK, nf - base);
        __syncthreads();
        for (int i = 0; i < 32; ++i) {
            const int idx = t + i * 256;
            const int row = idx >> 8, c4 = idx & 255;
            if (row < nt) {
                const int tok = g_fix[base + row];
                *(float4*)(XS + row * 1024 + c4 * 4) =
                    *(const float4*)(X + (size_t)tok * MDIM + c4 * 4);
            }
        }
        for (int eg = 0; eg < 4; ++eg) {
            __syncthreads();
            #pragma unroll
            for (int i = 0; i < 16; ++i) {
                const int idx = t + i * 256;
                const int row = idx >> 8, c4 = idx & 255;
                *(float4*)(WS + row * 1024 + c4 * 4) =
                    *(const float4*)(W + (size_t)(eg * 16 + row) * MDIM + c4 * 4);
            }
            __syncthreads();
            if (ts < nt) {
                const float* xr  = XS + ts * 1024;
                const float* wr0 = WS + el * 1024;
                const float* wr1 = WS + (el + 8) * 1024;
                float a0 = 0.f, a1 = 0.f, b0 = 0.f, b1 = 0.f;
                for (int k = 0; k < 512; k += 4) {
                    const float4 x0 = *(const float4*)(xr + k);
                    const float4 x1 = *(const float4*)(xr + 512 + k);
                    const float4 wa0 = *(const float4*)(wr0 + k);
                    const float4 wa1 = *(const float4*)(wr0 + 512 + k);
                    const float4 wb0 = *(const float4*)(wr1 + k);
                    const float4 wb1 = *(const float4*)(wr1 + 512 + k);
                    a0 = fmaf(x0.x, wa0.x, a0); a1 = fmaf(x1.x, wa1.x, a1);
                    b0 = fmaf(x0.x, wb0.x, b0); b1 = fmaf(x1.x, wb1.x, b1);
                    a0 = fmaf(x0.y, wa0.y, a0); a1 = fmaf(x1.y, wa1.y, a1);
                    b0 = fmaf(x0.y, wb0.y, b0); b1 = fmaf(x1.y, wb1.y, b1);
                    a0 = fmaf(x0.z, wa0.z, a0); a1 = fmaf(x1.z, wa1.z, a1);
                    b0 = fmaf(x0.z, wb0.z, b0); b1 = fmaf(x1.z, wb1.z, b1);
                    a0 = fmaf(x0.w, wa0.w, a0); a1 = fmaf(x1.w, wa1.w, a1);
                    b0 = fmaf(x0.w, wb0.w, b0); b1 = fmaf(x1.w, wb1.w, b1);
                }
                LG[ts * 64 + eg * 16 + el]     = a0 + a1;
                LG[ts * 64 + eg * 16 + el + 8] = b0 + b1;
            }
        }
        __syncthreads();
        if (t < nt) {
            const float* row = LG + t * 64;
            float v1 = -1e30f, v2 = -1e30f; int i1 = 0, i2 = 0;
            #pragma unroll
            for (int e = 0; e < NEXP; ++e) {
                const float v = row[e];
                if (v > v1)      { v2 = v1; i2 = i1; v1 = v; i1 = e; }
                else if (v > v2) { v2 = v;  i2 = e; }
            }
            const int tok = g_fix[base + t];
            g_flat[(size_t)tok * 2]     = (unsigned char)i1;
            g_flat[(size_t)tok * 2 + 1] = (unsigned char)i2;
        }
    }
}

// ---------------------------------------------------------------------------
// Counting sort (post-repair): hist -> scan -> rank
// ---------------------------------------------------------------------------
__global__ void hist_kernel()
{
    __shared__ int h[NEXP];
    const int t = threadIdx.x;
    if (t < NEXP) h[t] = 0;
    __syncthreads();
    const int base = blockIdx.x * SORT_CHUNK;
    #pragma unroll
    for (int q = 0; q < SORT_CHUNK / 256; ++q)
        atomicAdd(&h[g_flat[base + t + q * 256]], 1);
    __syncthreads();
    if (t < NEXP) g_bh[blockIdx.x * NEXP + t] = h[t];
}

__global__ void scan_kernel(float* __restrict__ splits_out)
{
    __shared__ int tot[NEXP];
    const int w    = threadIdx.x >> 5;
    const int lane = threadIdx.x & 31;
    #pragma unroll
    for (int ee = 0; ee < 2; ++ee) {
        const int e = w * 2 + ee;
        int v[16], s = 0;
        #pragma unroll
        for (int i = 0; i < 16; ++i) v[i] = g_bh[(lane * 16 + i) * NEXP + e];
        #pragma unroll
        for (int i = 0; i < 16; ++i) { const int x = v[i]; v[i] = s; s += x; }
        int run = s;
        #pragma unroll
        for (int off = 1; off < 32; off <<= 1) {
            const int n = __shfl_up_sync(0xffffffffu, run, off);
            if (lane >= off) run += n;
        }
        const int excl = run - s;
        #pragma unroll
        for (int i = 0; i < 16; ++i) g_bh[(lane * 16 + i) * NEXP + e] = v[i] + excl;
        if (lane == 31) tot[e] = run;
    }
    __syncthreads();
    if (threadIdx.x < NEXP) splits_out[threadIdx.x] = (float)tot[threadIdx.x];
    if (threadIdx.x == 0) {
        int base = 0;
        for (int e = 0; e < NEXP; ++e) { g_start[e] = base; base += tot[e]; }
    }
}

__global__ void rank_kernel(float* __restrict__ to_out, float* __restrict__ ro_out)
{
    __shared__ int cnt[NEXP];
    const int lane = threadIdx.x;
    cnt[lane]      = g_start[lane]      + g_bh[blockIdx.x * NEXP + lane];
    cnt[lane + 32] = g_start[lane + 32] + g_bh[blockIdx.x * NEXP + lane + 32];
    __syncwarp();
    const int base = blockIdx.x * SORT_CHUNK;
    #pragma unroll
    for (int it = 0; it < SORT_CHUNK / 32; ++it) {
        const int i = base + it * 32 + lane;
        const int e = g_flat[i];
        const unsigned peers = __match_any_sync(0xffffffffu, e);
        const int leader = __ffs(peers) - 1;
        const int prior  = __popc(peers & ((1u << lane) - 1));
        int b = 0;
        if (lane == leader) b = atomicAdd(&cnt[e], __popc(peers));
        b = __shfl_sync(peers, b, leader);
        const int p = b + prior;
        to_out[p] = (float)(i >> 1);
        ro_out[i] = (float)p;
    }
}

// ---------------------------------------------------------------------------
extern "C" void kernel_launch(void* const* d_in, const int* in_sizes, int n_in,
                              void* d_out, int out_size)
{
    const float* X = (const float*)d_in[0];   // [131072, 1024]
    const float* W = (const float*)d_in[1];   // [64, 1024]
    float* out = (float*)d_out;

    float* TO  = out;
    float* RO  = out + NK;
    float* CW  = out + 2 * NK;
    float* SPL = out + 3 * NK;
    float* PR  = out + 3 * NK + NEXP;

    cudaFuncSetAttribute(gate_kernel, cudaFuncAttributeMaxDynamicSharedMemorySize, GK_SMEM);
    cudaFuncSetAttribute(repair_kernel, cudaFuncAttributeMaxDynamicSharedMemorySize, RP_SMEM);

    wconv_kernel<<<128, 256>>>(W);
    gate_kernel<<<NTOK / TM, 128, GK_SMEM>>>(X, PR, CW);
    repair_kernel<<<REPAIR_BLOCKS, 256, RP_SMEM>>>(X, W);
    hist_kernel<<<SORT_BLOCKS, 256>>>();
    scan_kernel<<<1, 1024>>>(SPL);
    rank_kernel<<<SORT_BLOCKS, 32>>>(TO, RO);
}

// round 12
// speedup vs baseline: 2.3960x; 1.2187x over previous
#include <cuda_runtime.h>
#include <cstdint>

// ---------------------------------------------------------------------------
// LocalGate: N=131072, D=1024, E=64, K=2, GATE_ST.
// FFMA2 (fma.rn.f32x2) GEMM with Eigen-two-panel fp32 numerics (bitwise ==
// XLA:CPU reference): logit = fl(chain(k<512) + chain(k>=512)).
// Diagonal f32x2 pairing: acc families
//   D1[q][j] = (L[2q][2j],   L[2q+1][2j+1])  += (a2q,a2q+1) x (b2j,b2j+1)
//   D2[q][j] = (L[2q][2j+1], L[2q+1][2j])   += (a2q,a2q+1) x (b2j+1,b2j)
// Outputs: token_ordering | reversed_ordering | cw(=1) | input_splits | probs
// ---------------------------------------------------------------------------

#define NTOK   131072
#define MDIM   1024
#define NEXP   64
#define NK     (NTOK * 2)
#define TM     128
#define THREADS 128
#define KC     16
#define NCH    (MDIM / KC)          // 64
#define HALF_CH 32                  // Eigen kc=512 panel boundary
#define AST    132                  // A row stride (words)
#define BST    96                   // B row stride (words), 8 groups x 12
#define AWORDS (KC * AST)           // 2112
#define BWORDS (KC * BST)           // 1536
#define STGW   (AWORDS + BWORDS)    // 3648 words
#define STGB   (STGW * 4)           // 14592 B
#define NSTG   3
#define GK_SMEM (NSTG * STGB)       // 43776 -> 3 CTAs/SM

#define SORT_BLOCKS 512
#define SORT_CHUNK  (NK / SORT_BLOCKS)  // 512

__device__ unsigned char g_flat[NK];
__device__ int   g_bh[SORT_BLOCKS * NEXP];
__device__ int   g_start[NEXP];
__device__ float g_wpad[NCH * KC * BST];   // W re-laid: [c][k][eg*12 + (e&7)]
__device__ float g_panelL[NTOK * NEXP];    // panel-L spill (33.5 MB)

__device__ __forceinline__ uint32_t smem_u32(const void* p) {
    uint32_t a;
    asm("{ .reg .u64 t; cvta.to.shared.u64 t, %1; cvt.u32.u64 %0, t; }" : "=r"(a) : "l"(p));
    return a;
}
__device__ __forceinline__ void cp16(uint32_t dst, const void* src) {
    asm volatile("cp.async.cg.shared.global [%0], [%1], 16;" :: "r"(dst), "l"(src) : "memory");
}
// packed fp32 FMA: per-lane IEEE rn FMA (bitwise == scalar FFMA chain)
__device__ __forceinline__ void ffma2(float2& d, const float2& a, const float2& b) {
    asm("fma.rn.f32x2 %0, %1, %2, %0;"
        : "+l"(*reinterpret_cast<unsigned long long*>(&d))
        : "l"(*reinterpret_cast<const unsigned long long*>(&a)),
          "l"(*reinterpret_cast<const unsigned long long*>(&b)));
}

// ---------------------------------------------------------------------------
__global__ void prep_kernel(const float* __restrict__ W)
{
    const int id = blockIdx.x * 256 + threadIdx.x;       // 65536 threads
    if (id < NCH * KC * NEXP) {
        const int c = id >> 10;          // / (KC*NEXP)
        const int k = (id >> 6) & 15;
        const int e = id & 63;
        g_wpad[c * (KC * BST) + k * BST + (e >> 3) * 12 + (e & 7)] =
            W[(size_t)e * MDIM + c * KC + k];
    }
    if (id < SORT_BLOCKS * NEXP) g_bh[id] = 0;
}

// ---------------------------------------------------------------------------
__global__ void __launch_bounds__(THREADS, 3)
gate_kernel(const float* __restrict__ X,
            float* __restrict__ probs_out, float* __restrict__ cw_out)
{
    extern __shared__ float smf[];
    __shared__ int h[NEXP];
    const uint32_t sbase = smem_u32(smf);
    const int t    = threadIdx.x;
    const int w    = t >> 5;
    const int lane = t & 31;
    const int tg   = lane >> 3;          // token group 0..3
    const int eg   = lane & 7;           // expert group 0..7
    const int tok0 = blockIdx.x * TM;
    if (t < NEXP) h[t] = 0;

    // A staging: thread loads rows lr+32i (i=0..3), float4 at k4=lk4
    const int lr  = t >> 2;              // 0..31
    const int lk4 = t & 3;               // 0..3
    const float* xrow = X + (size_t)(tok0 + lr) * MDIM + lk4 * 4;

    float2 acc1[4][4], acc2[4][4];
    #pragma unroll
    for (int q = 0; q < 4; ++q)
        #pragma unroll
        for (int j = 0; j < 4; ++j) {
            acc1[q][j] = make_float2(0.f, 0.f);
            acc2[q][j] = make_float2(0.f, 0.f);
        }
    float4 pf[4];

    // B chunk copy: whole padded 6144B chunk, 3 cp16/thread
    auto cpB = [&](int c) {
        const int s = c % NSTG;
        const float* src = g_wpad + (size_t)c * (KC * BST);
        const uint32_t dst = sbase + s * STGB + AWORDS * 4;
        #pragma unroll
        for (int q = 0; q < 3; ++q)
            cp16(dst + (t + q * THREADS) * 16, src + (t + q * THREADS) * 4);
        asm volatile("cp.async.commit_group;" ::: "memory");
    };
    // A store (k-major, transposed from pf regs)
    auto stsA = [&](int c) {
        float* As = smf + (c % NSTG) * STGW;
        #pragma unroll
        for (int i = 0; i < 4; ++i) {
            const int row = lr + 32 * i;
            As[(lk4 * 4 + 0) * AST + row] = pf[i].x;
            As[(lk4 * 4 + 1) * AST + row] = pf[i].y;
            As[(lk4 * 4 + 2) * AST + row] = pf[i].z;
            As[(lk4 * 4 + 3) * AST + row] = pf[i].w;
        }
    };

    // prologue: A0 direct, A1 prefetched; B0,B1 in flight
    #pragma unroll
    for (int i = 0; i < 4; ++i) pf[i] = *(const float4*)(xrow + (size_t)i * 32 * MDIM);
    cpB(0); cpB(1);
    stsA(0);
    #pragma unroll
    for (int i = 0; i < 4; ++i) pf[i] = *(const float4*)(xrow + (size_t)i * 32 * MDIM + KC);
    asm volatile("cp.async.wait_group 1;" ::: "memory");
    __syncthreads();

    for (int c = 0; c < NCH; ++c) {
        const int s = c % NSTG;
        if (c + 2 < NCH) cpB(c + 2);

        const float* As = smf + s * STGW;
        const float* Bs = As + AWORDS;
        #pragma unroll
        for (int k = 0; k < KC; ++k) {
            const float* ak = As + k * AST + w * 32 + tg * 8;
            const float* bk = Bs + k * BST + eg * 12;
            float2 a[4], b[4], bs[4];
            #pragma unroll
            for (int q = 0; q < 4; ++q) a[q] = *(const float2*)(ak + 2 * q);
            #pragma unroll
            for (int j = 0; j < 4; ++j) b[j] = *(const float2*)(bk + 2 * j);
            #pragma unroll
            for (int j = 0; j < 4; ++j) bs[j] = make_float2(b[j].y, b[j].x);
            #pragma unroll
            for (int q = 0; q < 4; ++q)
                #pragma unroll
                for (int j = 0; j < 4; ++j) {
                    ffma2(acc1[q][j], a[q], b[j]);
                    ffma2(acc2[q][j], a[q], bs[j]);
                }
        }
        if (c + 1 < NCH) stsA(c + 1);
        if (c + 2 < NCH) {
            const float* xs = xrow + (c + 2) * KC;
            #pragma unroll
            for (int i = 0; i < 4; ++i) pf[i] = *(const float4*)(xs + (size_t)i * 32 * MDIM);
        }
        if (c + 2 < NCH) { asm volatile("cp.async.wait_group 1;" ::: "memory"); }
        else             { asm volatile("cp.async.wait_group 0;" ::: "memory"); }
        __syncthreads();

        if (c == HALF_CH - 1) {          // Eigen panel boundary: spill L, restart
            float* pl = g_panelL + ((size_t)(blockIdx.x * 4 + w)) * 2048 + lane * 4;
            #pragma unroll
            for (int q = 0; q < 4; ++q)
                #pragma unroll
                for (int jp = 0; jp < 2; ++jp) {
                    *(float4*)(pl + (q * 2 + jp) * 128) =
                        make_float4(acc1[q][2*jp].x, acc1[q][2*jp].y,
                                    acc1[q][2*jp+1].x, acc1[q][2*jp+1].y);
                    *(float4*)(pl + (8 + q * 2 + jp) * 128) =
                        make_float4(acc2[q][2*jp].x, acc2[q][2*jp].y,
                                    acc2[q][2*jp+1].x, acc2[q][2*jp+1].y);
                }
            #pragma unroll
            for (int q = 0; q < 4; ++q)
                #pragma unroll
                for (int j = 0; j < 4; ++j) {
                    acc1[q][j] = make_float2(0.f, 0.f);
                    acc2[q][j] = make_float2(0.f, 0.f);
                }
        }
    }

    // final = panelL + panelH (FADD, bitwise == Eigen C += panel updates)
    {
        const float* pl = g_panelL + ((size_t)(blockIdx.x * 4 + w)) * 2048 + lane * 4;
        #pragma unroll
        for (int q = 0; q < 4; ++q)
            #pragma unroll
            for (int jp = 0; jp < 2; ++jp) {
                float4 v1 = *(const float4*)(pl + (q * 2 + jp) * 128);
                float4 v2 = *(const float4*)(pl + (8 + q * 2 + jp) * 128);
                acc1[q][2*jp].x   += v1.x; acc1[q][2*jp].y   += v1.y;
                acc1[q][2*jp+1].x += v1.z; acc1[q][2*jp+1].y += v1.w;
                acc2[q][2*jp].x   += v2.x; acc2[q][2*jp].y   += v2.y;
                acc2[q][2*jp+1].x += v2.z; acc2[q][2*jp+1].y += v2.w;
            }
    }

    // ---- epilogue: per-token top-2 (exact) + softmax probs ----
    #pragma unroll
    for (int p = 0; p < 8; ++p) {
        const int q = p >> 1, r = p & 1;
        float lg[8];
        #pragma unroll
        for (int j = 0; j < 4; ++j) {
            lg[2*j]   = r ? acc2[q][j].y : acc1[q][j].x;
            lg[2*j+1] = r ? acc1[q][j].y : acc2[q][j].x;
        }
        float v1 = -1e30f, v2 = -1e30f; int i1 = 0, i2 = 0;
        #pragma unroll
        for (int m = 0; m < 8; ++m) {
            const float v = lg[m]; const int e = eg * 8 + m;
            if (v > v1)      { v2 = v1; i2 = i1; v1 = v; i1 = e; }
            else if (v > v2) { v2 = v;  i2 = e; }
        }
        #pragma unroll
        for (int msk = 1; msk < 8; msk <<= 1) {
            const float ov1 = __shfl_xor_sync(0xffffffffu, v1, msk);
            const int   oi1 = __shfl_xor_sync(0xffffffffu, i1, msk);
            const float ov2 = __shfl_xor_sync(0xffffffffu, v2, msk);
            const int   oi2 = __shfl_xor_sync(0xffffffffu, i2, msk);
            const bool g1 = (ov1 > v1) || (ov1 == v1 && oi1 < i1);
            if (g1) {
                const bool g2 = (v1 > ov2) || (v1 == ov2 && i1 < oi2);
                v2 = g2 ? v1 : ov2; i2 = g2 ? i1 : oi2;
                v1 = ov1; i1 = oi1;
            } else {
                const bool g2 = (ov1 > v2) || (ov1 == v2 && oi1 < i2);
                v2 = g2 ? ov1 : v2; i2 = g2 ? oi1 : i2;
            }
        }
        const int tok = tok0 + w * 32 + tg * 8 + p;
        if (eg == 0) {
            g_flat[(size_t)tok * 2]     = (unsigned char)i1;
            g_flat[(size_t)tok * 2 + 1] = (unsigned char)i2;
            atomicAdd(&h[i1], 1);
            atomicAdd(&h[i2], 1);
        }
        float ex[8], ssum = 0.f;
        #pragma unroll
        for (int m = 0; m < 8; ++m) { ex[m] = __expf(lg[m] - v1); ssum += ex[m]; }
        ssum += __shfl_xor_sync(0xffffffffu, ssum, 1);
        ssum += __shfl_xor_sync(0xffffffffu, ssum, 2);
        ssum += __shfl_xor_sync(0xffffffffu, ssum, 4);
        const float inv = 1.0f / ssum;
        float* pr = probs_out + (size_t)tok * NEXP + eg * 8;
        *(float4*)(pr)     = make_float4(ex[0]*inv, ex[1]*inv, ex[2]*inv, ex[3]*inv);
        *(float4*)(pr + 4) = make_float4(ex[4]*inv, ex[5]*inv, ex[6]*inv, ex[7]*inv);
    }
    cw_out[2 * tok0 + 2 * t]     = 1.0f;     // straight-through forward value
    cw_out[2 * tok0 + 2 * t + 1] = 1.0f;
    __syncthreads();
    if (t < NEXP) atomicAdd(&g_bh[(blockIdx.x >> 1) * NEXP + t], h[t]);
}

// ---------------------------------------------------------------------------
// Counting sort: scan -> rank (hist fused into gate)
// ---------------------------------------------------------------------------
__global__ void scan_kernel(float* __restrict__ splits_out)
{
    __shared__ int tot[NEXP];
    const int w    = threadIdx.x >> 5;
    const int lane = threadIdx.x & 31;
    #pragma unroll
    for (int ee = 0; ee < 2; ++ee) {
        const int e = w * 2 + ee;
        int v[16], s = 0;
        #pragma unroll
        for (int i = 0; i < 16; ++i) v[i] = g_bh[(lane * 16 + i) * NEXP + e];
        #pragma unroll
        for (int i = 0; i < 16; ++i) { const int x = v[i]; v[i] = s; s += x; }
        int run = s;
        #pragma unroll
        for (int off = 1; off < 32; off <<= 1) {
            const int n = __shfl_up_sync(0xffffffffu, run, off);
            if (lane >= off) run += n;
        }
        const int excl = run - s;
        #pragma unroll
        for (int i = 0; i < 16; ++i) g_bh[(lane * 16 + i) * NEXP + e] = v[i] + excl;
        if (lane == 31) tot[e] = run;
    }
    __syncthreads();
    if (threadIdx.x < NEXP) splits_out[threadIdx.x] = (float)tot[threadIdx.x];
    if (threadIdx.x == 0) {
        int base = 0;
        for (int e = 0; e < NEXP; ++e) { g_start[e] = base; base += tot[e]; }
    }
}

__global__ void rank_kernel(float* __restrict__ to_out, float* __restrict__ ro_out)
{
    __shared__ int cnt[NEXP];
    const int lane = threadIdx.x;
    cnt[lane]      = g_start[lane]      + g_bh[blockIdx.x * NEXP + lane];
    cnt[lane + 32] = g_start[lane + 32] + g_bh[blockIdx.x * NEXP + lane + 32];
    __syncwarp();
    const int base = blockIdx.x * SORT_CHUNK;
    #pragma unroll
    for (int it = 0; it < SORT_CHUNK / 32; ++it) {
        const int i = base + it * 32 + lane;
        const int e = g_flat[i];
        const unsigned peers = __match_any_sync(0xffffffffu, e);
        const int leader = __ffs(peers) - 1;
        const int prior  = __popc(peers & ((1u << lane) - 1));
        int b = 0;
        if (lane == leader) b = atomicAdd(&cnt[e], __popc(peers));
        b = __shfl_sync(peers, b, leader);
        const int p = b + prior;
        to_out[p] = (float)(i >> 1);
        ro_out[i] = (float)p;
    }
}

// ---------------------------------------------------------------------------
extern "C" void kernel_launch(void* const* d_in, const int* in_sizes, int n_in,
                              void* d_out, int out_size)
{
    const float* X = (const float*)d_in[0];   // [131072, 1024]
    const float* W = (const float*)d_in[1];   // [64, 1024]
    float* out = (float*)d_out;

    float* TO  = out;
    float* RO  = out + NK;
    float* CW  = out + 2 * NK;
    float* SPL = out + 3 * NK;
    float* PR  = out + 3 * NK + NEXP;

    cudaFuncSetAttribute(gate_kernel, cudaFuncAttributeMaxDynamicSharedMemorySize, GK_SMEM);

    prep_kernel<<<256, 256>>>(W);
    gate_kernel<<<NTOK / TM, THREADS, GK_SMEM>>>(X, PR, CW);
    scan_kernel<<<1, 1024>>>(SPL);
    rank_kernel<<<SORT_BLOCKS, 32>>>(TO, RO);
}